// round 8
// baseline (speedup 1.0000x reference)
#include <cuda_runtime.h>

#define OSC 2048
#define MH  4096
#define NTHR 256

#define XM_P  4104
#define XK_P  4100
#define XF_P  2052
#define SH_P  2052   // shifted 2048-vectors (k-state, out_m halves)

// ---------------- scratch (no allocs allowed) ----------------
__device__ __align__(16) float g_xm [4 * XM_P];
__device__ __align__(16) float g_xk1[4 * XK_P], g_xk2[4 * XK_P];
__device__ __align__(16) float g_xf1[4 * XF_P], g_xf2[4 * XF_P];
__device__ __align__(16) float g_sk1[4 * SH_P], g_sk2[4 * SH_P];  // k1_s/k2_s shifted
__device__ __align__(16) float g_so1[4 * SH_P], g_so2[4 * SH_P];  // out_m halves shifted
__device__ __align__(16) float g_mnew[MH];
__device__ __align__(16) float g_h1new[OSC], g_h2new[OSC];
__device__ __align__(16) float g_k1new[OSC], g_k2new[OSC];
__device__ __align__(16) float g_f1new[OSC], g_f2new[OSC];
__device__ __align__(16) float g_hp[OSC][12];  // h partials: [gi1(3), gi2(3), gh1(3), gh2(3)]
__device__ float g_hx[2];                       // x[2], x[5]
__device__ unsigned g_cnt_mo, g_cnt_hd;

__device__ __forceinline__ float sigm(float v) { return 1.0f / (1.0f + __expf(-v)); }
__device__ __forceinline__ int cls_off(int h) { return (4 - h) & 3; }

__device__ __forceinline__ float4 ldw(const float* p) {
    return __ldcs(reinterpret_cast<const float4*>(p));
}
__device__ __forceinline__ float4 ldx(const float* p) {
    return *reinterpret_cast<const float4*>(p);
}
__device__ __forceinline__ float4 ldcg4(const float* p) {
    return __ldcg(reinterpret_cast<const float4*>(p));
}
__device__ __forceinline__ float dot4(float4 a, float4 b) {
    return a.x * b.x + a.y * b.y + a.z * b.z + a.w * b.w;
}
__device__ __forceinline__ unsigned ld_acq(const unsigned* p) {
    unsigned v;
    asm volatile("ld.acquire.gpu.u32 %0, [%1];" : "=r"(v) : "l"(p) : "memory");
    return v;
}
__device__ __forceinline__ void wait_ge(const unsigned* c, unsigned tgt) {
    if (threadIdx.x == 0) {
        while (ld_acq(c) < tgt) __nanosleep(64);
    }
    __syncthreads();
}
__device__ __forceinline__ void signal(unsigned* c) {
    __threadfence();
    atomicAdd(c, 1u);
}

template <int NS>
__device__ __forceinline__ void blockReduce(float (&acc)[NS], float (&out)[NS]) {
    __shared__ float sm[NS][NTHR / 32];
    const int lane = threadIdx.x & 31;
    const int wid  = threadIdx.x >> 5;
#pragma unroll
    for (int s = 0; s < NS; s++) {
        float v = acc[s];
        v += __shfl_down_sync(0xffffffffu, v, 16);
        v += __shfl_down_sync(0xffffffffu, v, 8);
        v += __shfl_down_sync(0xffffffffu, v, 4);
        v += __shfl_down_sync(0xffffffffu, v, 2);
        v += __shfl_down_sync(0xffffffffu, v, 1);
        if (lane == 0) sm[s][wid] = v;
    }
    __syncthreads();
    if (threadIdx.x == 0) {
#pragma unroll
        for (int s = 0; s < NS; s++) {
            float v = 0.0f;
#pragma unroll
            for (int w = 0; w < NTHR / 32; w++) v += sm[s][w];
            out[s] = v;
        }
    }
}

// -------- single-stream GRU unit (m cell) --------
__device__ __forceinline__ void gru_unit_single(
    const float* __restrict__ wih, const float* __restrict__ whh,
    const float* __restrict__ bih, const float* __restrict__ bhh,
    const float* __restrict__ xbufs, int pad, int D,
    const float* __restrict__ hprev, int H, int j,
    float* __restrict__ newout)
{
    float acc[6] = {0, 0, 0, 0, 0, 0};
    const int head = (4 - (j & 3)) & 3;
    const float* xc = xbufs + head * pad + cls_off(head);
    const float* wr = wih + (size_t)j * D;
    const float* wz = wih + (size_t)(H + j) * D;
    const float* wn = wih + (size_t)(2 * H + j) * D;
    const int nvec = (D - head) >> 2;
    const int tail = D - head - (nvec << 2);

    if (threadIdx.x < (unsigned)head) {
        int d = threadIdx.x;
        float xv = xc[d];
        acc[0] += wr[d] * xv; acc[1] += wz[d] * xv; acc[2] += wn[d] * xv;
    }
    int c = threadIdx.x;
    for (; c + NTHR < nvec; c += 2 * NTHR) {
        int d0 = head + (c << 2);
        int d1 = d0 + (NTHR << 2);
        float4 a0 = ldw(wr + d0), b0 = ldw(wz + d0), e0 = ldw(wn + d0);
        float4 a1 = ldw(wr + d1), b1 = ldw(wz + d1), e1 = ldw(wn + d1);
        float4 x0 = ldx(xc + d0), x1 = ldx(xc + d1);
        acc[0] += dot4(a0, x0); acc[1] += dot4(b0, x0); acc[2] += dot4(e0, x0);
        acc[0] += dot4(a1, x1); acc[1] += dot4(b1, x1); acc[2] += dot4(e1, x1);
    }
    if (c < nvec) {
        int d0 = head + (c << 2);
        float4 a0 = ldw(wr + d0), b0 = ldw(wz + d0), e0 = ldw(wn + d0);
        float4 x0 = ldx(xc + d0);
        acc[0] += dot4(a0, x0); acc[1] += dot4(b0, x0); acc[2] += dot4(e0, x0);
    }
    if (threadIdx.x < (unsigned)tail) {
        int d = head + (nvec << 2) + threadIdx.x;
        float xv = xc[d];
        acc[0] += wr[d] * xv; acc[1] += wz[d] * xv; acc[2] += wn[d] * xv;
    }

    const float* ur = whh + (size_t)j * H;
    const float* uz = whh + (size_t)(H + j) * H;
    const float* un = whh + (size_t)(2 * H + j) * H;
    const int nvh = H >> 2;
    c = threadIdx.x;
    for (; c + NTHR < nvh; c += 2 * NTHR) {
        int d0 = c << 2, d1 = d0 + (NTHR << 2);
        float4 a0 = ldw(ur + d0), b0 = ldw(uz + d0), e0 = ldw(un + d0);
        float4 a1 = ldw(ur + d1), b1 = ldw(uz + d1), e1 = ldw(un + d1);
        float4 h0 = ldx(hprev + d0), h1v = ldx(hprev + d1);
        acc[3] += dot4(a0, h0); acc[4] += dot4(b0, h0); acc[5] += dot4(e0, h0);
        acc[3] += dot4(a1, h1v); acc[4] += dot4(b1, h1v); acc[5] += dot4(e1, h1v);
    }
    if (c < nvh) {
        int d0 = c << 2;
        float4 a0 = ldw(ur + d0), b0 = ldw(uz + d0), e0 = ldw(un + d0);
        float4 h0 = ldx(hprev + d0);
        acc[3] += dot4(a0, h0); acc[4] += dot4(b0, h0); acc[5] += dot4(e0, h0);
    }

    float s[6];
    blockReduce<6>(acc, s);
    if (threadIdx.x == 0) {
        float r = sigm(s[0] + bih[j] + s[3] + bhh[j]);
        float z = sigm(s[1] + bih[H + j] + s[4] + bhh[H + j]);
        float n = tanhf(s[2] + bih[2 * H + j] + r * (s[5] + bhh[2 * H + j]));
        newout[j] = (1.0f - z) * n + z * hprev[j];
    }
}

// -------- dual-stream GRU unit (k/f cells) --------
__device__ __forceinline__ void gru_unit_dual(
    const float* __restrict__ wih, const float* __restrict__ whh,
    const float* __restrict__ bih, const float* __restrict__ bhh,
    const float* __restrict__ x1bufs, const float* __restrict__ x2bufs, int pad, int D,
    const float* __restrict__ h1, const float* __restrict__ h2, int H, int j,
    float* __restrict__ out1, float* __restrict__ out2)
{
    float acc[12] = {0, 0, 0, 0, 0, 0, 0, 0, 0, 0, 0, 0};
    const int head = (4 - (j & 3)) & 3;
    const int off  = head * pad + cls_off(head);
    const float* x1c = x1bufs + off;
    const float* x2c = x2bufs + off;
    const float* wr = wih + (size_t)j * D;
    const float* wz = wih + (size_t)(H + j) * D;
    const float* wn = wih + (size_t)(2 * H + j) * D;
    const int nvec = (D - head) >> 2;
    const int tail = D - head - (nvec << 2);

    if (threadIdx.x < (unsigned)head) {
        int d = threadIdx.x;
        float a = x1c[d], b = x2c[d];
        float w0 = wr[d], w1 = wz[d], w2 = wn[d];
        acc[0] += w0 * a; acc[1] += w1 * a; acc[2] += w2 * a;
        acc[3] += w0 * b; acc[4] += w1 * b; acc[5] += w2 * b;
    }
    int c = threadIdx.x;
    for (; c + NTHR < nvec; c += 2 * NTHR) {
        int d0 = head + (c << 2), d1 = d0 + (NTHR << 2);
        float4 a0 = ldw(wr + d0), b0 = ldw(wz + d0), e0 = ldw(wn + d0);
        float4 a1 = ldw(wr + d1), b1 = ldw(wz + d1), e1 = ldw(wn + d1);
        float4 p0 = ldx(x1c + d0), q0 = ldx(x2c + d0);
        float4 p1 = ldx(x1c + d1), q1 = ldx(x2c + d1);
        acc[0] += dot4(a0, p0); acc[1] += dot4(b0, p0); acc[2] += dot4(e0, p0);
        acc[3] += dot4(a0, q0); acc[4] += dot4(b0, q0); acc[5] += dot4(e0, q0);
        acc[0] += dot4(a1, p1); acc[1] += dot4(b1, p1); acc[2] += dot4(e1, p1);
        acc[3] += dot4(a1, q1); acc[4] += dot4(b1, q1); acc[5] += dot4(e1, q1);
    }
    if (c < nvec) {
        int d0 = head + (c << 2);
        float4 a0 = ldw(wr + d0), b0 = ldw(wz + d0), e0 = ldw(wn + d0);
        float4 p0 = ldx(x1c + d0), q0 = ldx(x2c + d0);
        acc[0] += dot4(a0, p0); acc[1] += dot4(b0, p0); acc[2] += dot4(e0, p0);
        acc[3] += dot4(a0, q0); acc[4] += dot4(b0, q0); acc[5] += dot4(e0, q0);
    }
    if (threadIdx.x < (unsigned)tail) {
        int d = head + (nvec << 2) + threadIdx.x;
        float a = x1c[d], b = x2c[d];
        float w0 = wr[d], w1 = wz[d], w2 = wn[d];
        acc[0] += w0 * a; acc[1] += w1 * a; acc[2] += w2 * a;
        acc[3] += w0 * b; acc[4] += w1 * b; acc[5] += w2 * b;
    }

    const float* ur = whh + (size_t)j * H;
    const float* uz = whh + (size_t)(H + j) * H;
    const float* un = whh + (size_t)(2 * H + j) * H;
    const int nvh = H >> 2;
    c = threadIdx.x;
    for (; c + NTHR < nvh; c += 2 * NTHR) {
        int d0 = c << 2, d1 = d0 + (NTHR << 2);
        float4 a0 = ldw(ur + d0), b0 = ldw(uz + d0), e0 = ldw(un + d0);
        float4 a1 = ldw(ur + d1), b1 = ldw(uz + d1), e1 = ldw(un + d1);
        float4 p0 = ldx(h1 + d0), q0 = ldx(h2 + d0);
        float4 p1 = ldx(h1 + d1), q1 = ldx(h2 + d1);
        acc[6] += dot4(a0, p0); acc[7]  += dot4(b0, p0); acc[8]  += dot4(e0, p0);
        acc[9] += dot4(a0, q0); acc[10] += dot4(b0, q0); acc[11] += dot4(e0, q0);
        acc[6] += dot4(a1, p1); acc[7]  += dot4(b1, p1); acc[8]  += dot4(e1, p1);
        acc[9] += dot4(a1, q1); acc[10] += dot4(b1, q1); acc[11] += dot4(e1, q1);
    }
    if (c < nvh) {
        int d0 = c << 2;
        float4 a0 = ldw(ur + d0), b0 = ldw(uz + d0), e0 = ldw(un + d0);
        float4 p0 = ldx(h1 + d0), q0 = ldx(h2 + d0);
        acc[6] += dot4(a0, p0); acc[7]  += dot4(b0, p0); acc[8]  += dot4(e0, p0);
        acc[9] += dot4(a0, q0); acc[10] += dot4(b0, q0); acc[11] += dot4(e0, q0);
    }

    float s[12];
    blockReduce<12>(acc, s);
    if (threadIdx.x == 0) {
        float br = bih[j], bz = bih[H + j], bn = bih[2 * H + j];
        float cr = bhh[j], cz = bhh[H + j], cn = bhh[2 * H + j];
        {
            float r = sigm(s[0] + br + s[6] + cr);
            float z = sigm(s[1] + bz + s[7] + cz);
            float n = tanhf(s[2] + bn + r * (s[8] + cn));
            out1[j] = (1.0f - z) * n + z * h1[j];
        }
        {
            float r = sigm(s[3] + br + s[9] + cr);
            float z = sigm(s[4] + bz + s[10] + cz);
            float n = tanhf(s[5] + bn + r * (s[11] + cn));
            out2[j] = (1.0f - z) * n + z * h2[j];
        }
    }
}

// ---------------- K0: prep, one (copy,i) pair per thread ----------------
__global__ __launch_bounds__(NTHR) void k_prep(
    const float* __restrict__ x,
    const float* __restrict__ h1s, const float* __restrict__ h2s,
    const float* __restrict__ k1s, const float* __restrict__ k2s,
    const float* __restrict__ f1s, const float* __restrict__ f2s)
{
    int idx = blockIdx.x * blockDim.x + threadIdx.x;   // [0, 4*OSC)
    int h = idx >> 11;
    int i = idx & (OSC - 1);
    if (idx == 0) {
#pragma unroll
        for (int c = 0; c < 4; c++) {
            int o = cls_off(c);
            g_xm [c * XM_P + o + 0] = x[0];
            g_xm [c * XM_P + o + 1] = x[1];
            g_xm [c * XM_P + o + 2] = x[8];
            g_xm [c * XM_P + o + 3] = x[9];
            g_xm [c * XM_P + o + 4] = x[10];
            g_xk1[c * XK_P + o] = x[3]; g_xk2[c * XK_P + o] = x[6];
            g_xf1[c * XF_P + o] = x[4]; g_xf2[c * XF_P + o] = x[7];
        }
        g_hx[0] = x[2];
        g_hx[1] = x[5];
        g_cnt_mo = 0u;
        g_cnt_hd = 0u;
    }
    {
        float h1v = h1s[i], h2v = h2s[i], f1v = f1s[i], f2v = f2s[i];
        float k1v = k1s[i], k2v = k2s[i];
        int o = cls_off(h);
        g_xm [h * XM_P + o + 5 + i]        = h1v;
        g_xm [h * XM_P + o + 5 + OSC + i]  = h2v;
        g_xk1[h * XK_P + o + 1 + i]        = h1v;
        g_xk1[h * XK_P + o + 1 + OSC + i]  = f1v;
        g_xk2[h * XK_P + o + 1 + i]        = h2v;
        g_xk2[h * XK_P + o + 1 + OSC + i]  = f2v;
        g_xf1[h * XF_P + o + 1 + i]        = f1v;
        g_xf2[h * XF_P + o + 1 + i]        = f2v;
        g_sk1[h * SH_P + h + i] = k1v;
        g_sk2[h * SH_P + h + i] = k2v;
    }
}

// ---------------- K1: m + k + f + h_ind (all input-only; no sync) ----------------
// blocks: [0,4096) m | [4096,6144) k | [6144,8192) f | [8192,10240) h_ind
__global__ __launch_bounds__(NTHR) void k_main(
    const float* __restrict__ m_s,
    const float* __restrict__ h1s, const float* __restrict__ h2s,
    const float* __restrict__ k1s, const float* __restrict__ k2s,
    const float* __restrict__ f1s, const float* __restrict__ f2s,
    const float* __restrict__ m_wih, const float* __restrict__ m_whh,
    const float* __restrict__ m_bih, const float* __restrict__ m_bhh,
    const float* __restrict__ h_wih, const float* __restrict__ h_whh,
    const float* __restrict__ k_wih, const float* __restrict__ k_whh,
    const float* __restrict__ k_bih, const float* __restrict__ k_bhh,
    const float* __restrict__ f_wih, const float* __restrict__ f_whh,
    const float* __restrict__ f_bih, const float* __restrict__ f_bhh)
{
    const int b = blockIdx.x;
    const int tid = threadIdx.x;

    if (b < 4096) {
        gru_unit_single(m_wih, m_whh, m_bih, m_bhh, g_xm, XM_P, 5 + 2 * OSC,
                        m_s, MH, b, g_mnew);
    } else if (b < 6144) {
        gru_unit_dual(k_wih, k_whh, k_bih, k_bhh, g_xk1, g_xk2, XK_P, 1 + 2 * OSC,
                      k1s, k2s, OSC, b - 4096, g_k1new, g_k2new);
    } else if (b < 8192) {
        gru_unit_dual(f_wih, f_whh, f_bih, f_bhh, g_xf1, g_xf2, XF_P, 1 + OSC,
                      f1s, f2s, OSC, b - 6144, g_f1new, g_f2new);
    } else {
        // ---- h_ind: whh + wih col0 + wih cols [2049,4097) -> partials ----
        const int j = b - 8192;
        const int a = (j + 1) & 3;
        const int head = (4 - a) & 3;
        float acc[12] = {0,0,0,0,0,0,0,0,0,0,0,0};

        // whh (aligned): 512 vec cols, 2 per thread
        {
            const float* ur = h_whh + (size_t)j * OSC;
            const float* uz = ur + (size_t)OSC * OSC;
            const float* un = uz + (size_t)OSC * OSC;
            int d0 = tid << 2, d1 = d0 + 1024;
            float4 u0 = ldw(ur + d0), u1 = ldw(uz + d0), u2 = ldw(un + d0);
            float4 u3 = ldw(ur + d1), u4 = ldw(uz + d1), u5 = ldw(un + d1);
            float4 p0 = ldx(h1s + d0), p1 = ldx(h1s + d1);
            float4 q0 = ldx(h2s + d0), q1 = ldx(h2s + d1);
            acc[6] = dot4(u0, p0) + dot4(u3, p1);
            acc[7] = dot4(u1, p0) + dot4(u4, p1);
            acc[8] = dot4(u2, p0) + dot4(u5, p1);
            acc[9]  = dot4(u0, q0) + dot4(u3, q1);
            acc[10] = dot4(u1, q0) + dot4(u4, q1);
            acc[11] = dot4(u2, q0) + dot4(u5, q1);
        }
        // wih independent segment [2049, 4097): x = k1_s/k2_s
        {
            const float* wr = h_wih + (size_t)j * 4097 + 2049;
            const float* wz = wr + (size_t)OSC * 4097;
            const float* wn = wz + (size_t)OSC * 4097;
            const float* xk1 = g_sk1 + a * SH_P + a;
            const float* xk2 = g_sk2 + a * SH_P + a;
            const int nv = (2048 - head) >> 2;
            int e0 = head + (tid << 2);
            float4 w0 = ldw(wr + e0), w1 = ldw(wz + e0), w2 = ldw(wn + e0);
            float4 xp = ldx(xk1 + e0), xq = ldx(xk2 + e0);
            acc[0] += dot4(w0, xp); acc[1] += dot4(w1, xp); acc[2] += dot4(w2, xp);
            acc[3] += dot4(w0, xq); acc[4] += dot4(w1, xq); acc[5] += dot4(w2, xq);
            if (tid + NTHR < nv) {
                int e1 = head + ((tid + NTHR) << 2);
                float4 w3 = ldw(wr + e1), w4 = ldw(wz + e1), w5 = ldw(wn + e1);
                float4 xp1 = ldx(xk1 + e1), xq1 = ldx(xk2 + e1);
                acc[0] += dot4(w3, xp1); acc[1] += dot4(w4, xp1); acc[2] += dot4(w5, xp1);
                acc[3] += dot4(w3, xq1); acc[4] += dot4(w4, xq1); acc[5] += dot4(w5, xq1);
            }
            if (tid < head) {
                float xa = xk1[tid], xb = xk2[tid];
                float s0 = wr[tid], s1 = wz[tid], s2 = wn[tid];
                acc[0] += s0 * xa; acc[1] += s1 * xa; acc[2] += s2 * xa;
                acc[3] += s0 * xb; acc[4] += s1 * xb; acc[5] += s2 * xb;
            }
            const int tstart = head + (nv << 2);
            const int tcount = 2048 - tstart;
            if (tid >= 32 && tid - 32 < tcount) {
                int t = tstart + (tid - 32);
                float xa = xk1[t], xb = xk2[t];
                float s0 = wr[t], s1 = wz[t], s2 = wn[t];
                acc[0] += s0 * xa; acc[1] += s1 * xa; acc[2] += s2 * xa;
                acc[3] += s0 * xb; acc[4] += s1 * xb; acc[5] += s2 * xb;
            }
            if (tid == 64) {
                // wih col 0 (x = h observation scalars)
                const float* w0p = h_wih + (size_t)j * 4097;
                float w0 = w0p[0];
                float w1 = w0p[(size_t)OSC * 4097];
                float w2 = w0p[(size_t)2 * OSC * 4097];
                float hx1 = g_hx[0], hx2 = g_hx[1];
                acc[0] += w0 * hx1; acc[1] += w1 * hx1; acc[2] += w2 * hx1;
                acc[3] += w0 * hx2; acc[4] += w1 * hx2; acc[5] += w2 * hx2;
            }
        }
        float s[12];
        blockReduce<12>(acc, s);
        if (tid == 0) {
#pragma unroll
            for (int i = 0; i < 12; i++) g_hp[j][i] = s[i];
        }
    }
}

// ---------------- K2 (fused tail): mout + h_dep + heads ----------------
// blocks: [0,4096) mout | [4096,6144) h_dep | [6144,6150) heads
__global__ __launch_bounds__(NTHR) void k_tail(
    const float* __restrict__ h1s, const float* __restrict__ h2s,
    const float* __restrict__ m_ow, const float* __restrict__ m_ob,
    const float* __restrict__ h_wih,
    const float* __restrict__ h_bih, const float* __restrict__ h_bhh,
    const float* __restrict__ h_ow, const float* __restrict__ h_ob,
    const float* __restrict__ k_ow, const float* __restrict__ k_ob,
    const float* __restrict__ f_ow, const float* __restrict__ f_ob,
    float* __restrict__ out)
{
    const int b = blockIdx.x;
    const int tid = threadIdx.x;

    if (b < 4096) {
        // ---- mout (g_mnew final at kernel boundary; no wait) ----
        const int r = b;
        const float* wr = m_ow + (size_t)r * MH;
        int d0 = tid << 2;
        float4 a0 = ldw(wr + d0),        a1 = ldw(wr + d0 + 1024);
        float4 a2 = ldw(wr + d0 + 2048), a3 = ldw(wr + d0 + 3072);
        float4 m0 = ldx(g_mnew + d0),        m1 = ldx(g_mnew + d0 + 1024);
        float4 m2 = ldx(g_mnew + d0 + 2048), m3 = ldx(g_mnew + d0 + 3072);
        float acc[1];
        acc[0] = dot4(a0, m0) + dot4(a1, m1) + dot4(a2, m2) + dot4(a3, m3);
        float s[1];
        blockReduce<1>(acc, s);
        if (tid == 0) {
            float v = s[0] + m_ob[r];
            if (r < OSC) {
#pragma unroll
                for (int o = 0; o < 4; o++) g_so1[o * SH_P + o + r] = v;
            } else {
                int rr = r - OSC;
#pragma unroll
                for (int o = 0; o < 4; o++) g_so2[o * SH_P + o + rr] = v;
            }
            signal(&g_cnt_mo);
        }
    } else if (b < 6144) {
        // ---- h_dep: prefetch weights -> wait for mout -> FMAs + gates ----
        const int j = b - 4096;
        const int a = (j + 1) & 3;
        const int head = (4 - a) & 3;
        const int nv = (2048 - head) >> 2;
        const float* wr = h_wih + (size_t)j * 4097 + 1;
        const float* wz = wr + (size_t)OSC * 4097;
        const float* wn = wz + (size_t)OSC * 4097;

        // weight prefetch (independent of out_m) — streams during mout phase
        int e0 = head + (tid << 2);
        float4 w0 = ldw(wr + e0), w1 = ldw(wz + e0), w2 = ldw(wn + e0);
        bool ok1 = (tid + NTHR < nv);
        int e1 = head + ((tid + NTHR) << 2);
        float4 w3 = {0,0,0,0}, w4 = {0,0,0,0}, w5 = {0,0,0,0};
        if (ok1) { w3 = ldw(wr + e1); w4 = ldw(wz + e1); w5 = ldw(wn + e1); }
        float hs0 = 0, hs1 = 0, hs2 = 0, ts0 = 0, ts1 = 0, ts2 = 0;
        if (tid < head) { hs0 = wr[tid]; hs1 = wz[tid]; hs2 = wn[tid]; }
        const int tstart = head + (nv << 2);
        const int tcount = 2048 - tstart;
        bool do_tail = (tid >= 32 && tid - 32 < tcount);
        int tt = tstart + (tid - 32);
        if (do_tail) { ts0 = wr[tt]; ts1 = wz[tt]; ts2 = wn[tt]; }

        wait_ge(&g_cnt_mo, 4096u);

        const float* xo1 = g_so1 + a * SH_P + a;
        const float* xo2 = g_so2 + a * SH_P + a;
        float acc[6] = {0, 0, 0, 0, 0, 0};
        {
            float4 p0 = ldcg4(xo1 + e0), q0 = ldcg4(xo2 + e0);
            acc[0] += dot4(w0, p0); acc[1] += dot4(w1, p0); acc[2] += dot4(w2, p0);
            acc[3] += dot4(w0, q0); acc[4] += dot4(w1, q0); acc[5] += dot4(w2, q0);
            if (ok1) {
                float4 p1 = ldcg4(xo1 + e1), q1 = ldcg4(xo2 + e1);
                acc[0] += dot4(w3, p1); acc[1] += dot4(w4, p1); acc[2] += dot4(w5, p1);
                acc[3] += dot4(w3, q1); acc[4] += dot4(w4, q1); acc[5] += dot4(w5, q1);
            }
        }
        if (tid < head) {
            float xa = __ldcg(xo1 + tid), xb = __ldcg(xo2 + tid);
            acc[0] += hs0 * xa; acc[1] += hs1 * xa; acc[2] += hs2 * xa;
            acc[3] += hs0 * xb; acc[4] += hs1 * xb; acc[5] += hs2 * xb;
        }
        if (do_tail) {
            float xa = __ldcg(xo1 + tt), xb = __ldcg(xo2 + tt);
            acc[0] += ts0 * xa; acc[1] += ts1 * xa; acc[2] += ts2 * xa;
            acc[3] += ts0 * xb; acc[4] += ts1 * xb; acc[5] += ts2 * xb;
        }
        float s[6];
        blockReduce<6>(acc, s);
        if (tid == 0) {
            float p[12];
#pragma unroll
            for (int i = 0; i < 12; i++) p[i] = g_hp[j][i];
            float br = h_bih[j], bz = h_bih[OSC + j], bn = h_bih[2 * OSC + j];
            float cr = h_bhh[j], cz = h_bhh[OSC + j], cn = h_bhh[2 * OSC + j];
            {
                float r = sigm(p[0] + s[0] + br + p[6] + cr);
                float z = sigm(p[1] + s[1] + bz + p[7] + cz);
                float n = tanhf(p[2] + s[2] + bn + r * (p[8] + cn));
                g_h1new[j] = (1.0f - z) * n + z * h1s[j];
            }
            {
                float r = sigm(p[3] + s[3] + br + p[9] + cr);
                float z = sigm(p[4] + s[4] + bz + p[10] + cz);
                float n = tanhf(p[5] + s[5] + bn + r * (p[11] + cn));
                g_h2new[j] = (1.0f - z) * n + z * h2s[j];
            }
            signal(&g_cnt_hd);
        }
    } else {
        // ---- heads: prefetch weights -> wait for h_dep -> dot ----
        const int hb = b - 6144;
        const float* vec;
        const float* w;
        const float* bp;
        bool needs_h = (hb == 0 || hb == 3);
        switch (hb) {
            case 0: vec = g_h1new; w = h_ow; bp = h_ob; break;
            case 1: vec = g_k1new; w = k_ow; bp = k_ob; break;
            case 2: vec = g_f1new; w = f_ow; bp = f_ob; break;
            case 3: vec = g_h2new; w = h_ow; bp = h_ob; break;
            case 4: vec = g_k2new; w = k_ow; bp = k_ob; break;
            default: vec = g_f2new; w = f_ow; bp = f_ob; break;
        }
        int d0 = tid << 2;
        float4 a0 = ldx(w + d0), a1 = ldx(w + d0 + 1024);
        if (needs_h) wait_ge(&g_cnt_hd, 2048u);
        float4 v0 = ldcg4(vec + d0), v1 = ldcg4(vec + d0 + 1024);
        float acc[1];
        acc[0] = dot4(a0, v0) + dot4(a1, v1);
        float s[1];
        blockReduce<1>(acc, s);
        if (tid == 0) out[hb] = s[0] + bp[0];
    }
}

// ---------------- launch ----------------
extern "C" void kernel_launch(void* const* d_in, const int* in_sizes, int n_in,
                              void* d_out, int out_size)
{
    const float* x      = (const float*)d_in[0];
    const float* m_s    = (const float*)d_in[1];
    const float* h1_s   = (const float*)d_in[2];
    const float* h2_s   = (const float*)d_in[3];
    const float* k1_s   = (const float*)d_in[4];
    const float* k2_s   = (const float*)d_in[5];
    const float* f1_s   = (const float*)d_in[6];
    const float* f2_s   = (const float*)d_in[7];
    const float* m_wih  = (const float*)d_in[8];
    const float* m_whh  = (const float*)d_in[9];
    const float* m_bih  = (const float*)d_in[10];
    const float* m_bhh  = (const float*)d_in[11];
    const float* m_ow   = (const float*)d_in[12];
    const float* m_ob   = (const float*)d_in[13];
    const float* h_wih  = (const float*)d_in[14];
    const float* h_whh  = (const float*)d_in[15];
    const float* h_bih  = (const float*)d_in[16];
    const float* h_bhh  = (const float*)d_in[17];
    const float* h_ow   = (const float*)d_in[18];
    const float* h_ob   = (const float*)d_in[19];
    const float* k_wih  = (const float*)d_in[20];
    const float* k_whh  = (const float*)d_in[21];
    const float* k_bih  = (const float*)d_in[22];
    const float* k_bhh  = (const float*)d_in[23];
    const float* k_ow   = (const float*)d_in[24];
    const float* k_ob   = (const float*)d_in[25];
    const float* f_wih  = (const float*)d_in[26];
    const float* f_whh  = (const float*)d_in[27];
    const float* f_bih  = (const float*)d_in[28];
    const float* f_bhh  = (const float*)d_in[29];
    const float* f_ow   = (const float*)d_in[30];
    const float* f_ob   = (const float*)d_in[31];
    float* out = (float*)d_out;

    k_prep<<<(4 * OSC) / NTHR, NTHR>>>(x, h1_s, h2_s, k1_s, k2_s, f1_s, f2_s);
    k_main<<<10240, NTHR>>>(m_s, h1_s, h2_s, k1_s, k2_s, f1_s, f2_s,
                            m_wih, m_whh, m_bih, m_bhh,
                            h_wih, h_whh,
                            k_wih, k_whh, k_bih, k_bhh,
                            f_wih, f_whh, f_bih, f_bhh);
    k_tail<<<6150, NTHR>>>(h1_s, h2_s, m_ow, m_ob,
                           h_wih, h_bih, h_bhh,
                           h_ow, h_ob, k_ow, k_ob, f_ow, f_ob,
                           out);
}

// round 9
// speedup vs baseline: 1.0250x; 1.0250x over previous
#include <cuda_runtime.h>

#define OSC 2048
#define MH  4096
#define NTHR 256

#define XM_P  4104
#define XK_P  4100
#define XF_P  2052
#define SH_P  2052   // shifted 2048-vectors (k-state, out_m halves)

// ---------------- scratch (no allocs allowed) ----------------
__device__ __align__(16) float g_xm [4 * XM_P];
__device__ __align__(16) float g_xk1[4 * XK_P], g_xk2[4 * XK_P];
__device__ __align__(16) float g_xf1[4 * XF_P], g_xf2[4 * XF_P];
__device__ __align__(16) float g_sk1[4 * SH_P], g_sk2[4 * SH_P];  // k1_s/k2_s shifted
__device__ __align__(16) float g_so1[4 * SH_P], g_so2[4 * SH_P];  // out_m halves shifted
__device__ __align__(16) float g_mnew[MH];
__device__ __align__(16) float g_h1new[OSC], g_h2new[OSC];
__device__ __align__(16) float g_k1new[OSC], g_k2new[OSC];
__device__ __align__(16) float g_f1new[OSC], g_f2new[OSC];
__device__ __align__(16) float g_hp[OSC][12];  // h partials: [gi1(3), gi2(3), gh1(3), gh2(3)]
__device__ float g_hx[2];                       // x[2], x[5]

__device__ __forceinline__ float sigm(float v) { return 1.0f / (1.0f + __expf(-v)); }
__device__ __forceinline__ int cls_off(int h) { return (4 - h) & 3; }

__device__ __forceinline__ float4 ldw(const float* p) {
    return __ldcs(reinterpret_cast<const float4*>(p));
}
__device__ __forceinline__ float4 ldx(const float* p) {
    return *reinterpret_cast<const float4*>(p);
}
__device__ __forceinline__ float dot4(float4 a, float4 b) {
    return a.x * b.x + a.y * b.y + a.z * b.z + a.w * b.w;
}

template <int NS>
__device__ __forceinline__ void blockReduce(float (&acc)[NS], float (&out)[NS]) {
    __shared__ float sm[NS][NTHR / 32];
    const int lane = threadIdx.x & 31;
    const int wid  = threadIdx.x >> 5;
#pragma unroll
    for (int s = 0; s < NS; s++) {
        float v = acc[s];
        v += __shfl_down_sync(0xffffffffu, v, 16);
        v += __shfl_down_sync(0xffffffffu, v, 8);
        v += __shfl_down_sync(0xffffffffu, v, 4);
        v += __shfl_down_sync(0xffffffffu, v, 2);
        v += __shfl_down_sync(0xffffffffu, v, 1);
        if (lane == 0) sm[s][wid] = v;
    }
    __syncthreads();
    if (threadIdx.x == 0) {
#pragma unroll
        for (int s = 0; s < NS; s++) {
            float v = 0.0f;
#pragma unroll
            for (int w = 0; w < NTHR / 32; w++) v += sm[s][w];
            out[s] = v;
        }
    }
}

// -------- single-stream GRU unit (m cell) --------
__device__ __forceinline__ void gru_unit_single(
    const float* __restrict__ wih, const float* __restrict__ whh,
    const float* __restrict__ bih, const float* __restrict__ bhh,
    const float* __restrict__ xbufs, int pad, int D,
    const float* __restrict__ hprev, int H, int j,
    float* __restrict__ newout)
{
    float acc[6] = {0, 0, 0, 0, 0, 0};
    const int head = (4 - (j & 3)) & 3;
    const float* xc = xbufs + head * pad + cls_off(head);
    const float* wr = wih + (size_t)j * D;
    const float* wz = wih + (size_t)(H + j) * D;
    const float* wn = wih + (size_t)(2 * H + j) * D;
    const int nvec = (D - head) >> 2;
    const int tail = D - head - (nvec << 2);

    if (threadIdx.x < (unsigned)head) {
        int d = threadIdx.x;
        float xv = xc[d];
        acc[0] += wr[d] * xv; acc[1] += wz[d] * xv; acc[2] += wn[d] * xv;
    }
    int c = threadIdx.x;
    for (; c + NTHR < nvec; c += 2 * NTHR) {
        int d0 = head + (c << 2);
        int d1 = d0 + (NTHR << 2);
        float4 a0 = ldw(wr + d0), b0 = ldw(wz + d0), e0 = ldw(wn + d0);
        float4 a1 = ldw(wr + d1), b1 = ldw(wz + d1), e1 = ldw(wn + d1);
        float4 x0 = ldx(xc + d0), x1 = ldx(xc + d1);
        acc[0] += dot4(a0, x0); acc[1] += dot4(b0, x0); acc[2] += dot4(e0, x0);
        acc[0] += dot4(a1, x1); acc[1] += dot4(b1, x1); acc[2] += dot4(e1, x1);
    }
    if (c < nvec) {
        int d0 = head + (c << 2);
        float4 a0 = ldw(wr + d0), b0 = ldw(wz + d0), e0 = ldw(wn + d0);
        float4 x0 = ldx(xc + d0);
        acc[0] += dot4(a0, x0); acc[1] += dot4(b0, x0); acc[2] += dot4(e0, x0);
    }
    if (threadIdx.x < (unsigned)tail) {
        int d = head + (nvec << 2) + threadIdx.x;
        float xv = xc[d];
        acc[0] += wr[d] * xv; acc[1] += wz[d] * xv; acc[2] += wn[d] * xv;
    }

    const float* ur = whh + (size_t)j * H;
    const float* uz = whh + (size_t)(H + j) * H;
    const float* un = whh + (size_t)(2 * H + j) * H;
    const int nvh = H >> 2;
    c = threadIdx.x;
    for (; c + NTHR < nvh; c += 2 * NTHR) {
        int d0 = c << 2, d1 = d0 + (NTHR << 2);
        float4 a0 = ldw(ur + d0), b0 = ldw(uz + d0), e0 = ldw(un + d0);
        float4 a1 = ldw(ur + d1), b1 = ldw(uz + d1), e1 = ldw(un + d1);
        float4 h0 = ldx(hprev + d0), h1v = ldx(hprev + d1);
        acc[3] += dot4(a0, h0); acc[4] += dot4(b0, h0); acc[5] += dot4(e0, h0);
        acc[3] += dot4(a1, h1v); acc[4] += dot4(b1, h1v); acc[5] += dot4(e1, h1v);
    }
    if (c < nvh) {
        int d0 = c << 2;
        float4 a0 = ldw(ur + d0), b0 = ldw(uz + d0), e0 = ldw(un + d0);
        float4 h0 = ldx(hprev + d0);
        acc[3] += dot4(a0, h0); acc[4] += dot4(b0, h0); acc[5] += dot4(e0, h0);
    }

    float s[6];
    blockReduce<6>(acc, s);
    if (threadIdx.x == 0) {
        float r = sigm(s[0] + bih[j] + s[3] + bhh[j]);
        float z = sigm(s[1] + bih[H + j] + s[4] + bhh[H + j]);
        float n = tanhf(s[2] + bih[2 * H + j] + r * (s[5] + bhh[2 * H + j]));
        newout[j] = (1.0f - z) * n + z * hprev[j];
    }
}

// -------- dual-stream GRU unit (k/f cells) --------
__device__ __forceinline__ void gru_unit_dual(
    const float* __restrict__ wih, const float* __restrict__ whh,
    const float* __restrict__ bih, const float* __restrict__ bhh,
    const float* __restrict__ x1bufs, const float* __restrict__ x2bufs, int pad, int D,
    const float* __restrict__ h1, const float* __restrict__ h2, int H, int j,
    float* __restrict__ out1, float* __restrict__ out2)
{
    float acc[12] = {0, 0, 0, 0, 0, 0, 0, 0, 0, 0, 0, 0};
    const int head = (4 - (j & 3)) & 3;
    const int off  = head * pad + cls_off(head);
    const float* x1c = x1bufs + off;
    const float* x2c = x2bufs + off;
    const float* wr = wih + (size_t)j * D;
    const float* wz = wih + (size_t)(H + j) * D;
    const float* wn = wih + (size_t)(2 * H + j) * D;
    const int nvec = (D - head) >> 2;
    const int tail = D - head - (nvec << 2);

    if (threadIdx.x < (unsigned)head) {
        int d = threadIdx.x;
        float a = x1c[d], b = x2c[d];
        float w0 = wr[d], w1 = wz[d], w2 = wn[d];
        acc[0] += w0 * a; acc[1] += w1 * a; acc[2] += w2 * a;
        acc[3] += w0 * b; acc[4] += w1 * b; acc[5] += w2 * b;
    }
    int c = threadIdx.x;
    for (; c + NTHR < nvec; c += 2 * NTHR) {
        int d0 = head + (c << 2), d1 = d0 + (NTHR << 2);
        float4 a0 = ldw(wr + d0), b0 = ldw(wz + d0), e0 = ldw(wn + d0);
        float4 a1 = ldw(wr + d1), b1 = ldw(wz + d1), e1 = ldw(wn + d1);
        float4 p0 = ldx(x1c + d0), q0 = ldx(x2c + d0);
        float4 p1 = ldx(x1c + d1), q1 = ldx(x2c + d1);
        acc[0] += dot4(a0, p0); acc[1] += dot4(b0, p0); acc[2] += dot4(e0, p0);
        acc[3] += dot4(a0, q0); acc[4] += dot4(b0, q0); acc[5] += dot4(e0, q0);
        acc[0] += dot4(a1, p1); acc[1] += dot4(b1, p1); acc[2] += dot4(e1, p1);
        acc[3] += dot4(a1, q1); acc[4] += dot4(b1, q1); acc[5] += dot4(e1, q1);
    }
    if (c < nvec) {
        int d0 = head + (c << 2);
        float4 a0 = ldw(wr + d0), b0 = ldw(wz + d0), e0 = ldw(wn + d0);
        float4 p0 = ldx(x1c + d0), q0 = ldx(x2c + d0);
        acc[0] += dot4(a0, p0); acc[1] += dot4(b0, p0); acc[2] += dot4(e0, p0);
        acc[3] += dot4(a0, q0); acc[4] += dot4(b0, q0); acc[5] += dot4(e0, q0);
    }
    if (threadIdx.x < (unsigned)tail) {
        int d = head + (nvec << 2) + threadIdx.x;
        float a = x1c[d], b = x2c[d];
        float w0 = wr[d], w1 = wz[d], w2 = wn[d];
        acc[0] += w0 * a; acc[1] += w1 * a; acc[2] += w2 * a;
        acc[3] += w0 * b; acc[4] += w1 * b; acc[5] += w2 * b;
    }

    const float* ur = whh + (size_t)j * H;
    const float* uz = whh + (size_t)(H + j) * H;
    const float* un = whh + (size_t)(2 * H + j) * H;
    const int nvh = H >> 2;
    c = threadIdx.x;
    for (; c + NTHR < nvh; c += 2 * NTHR) {
        int d0 = c << 2, d1 = d0 + (NTHR << 2);
        float4 a0 = ldw(ur + d0), b0 = ldw(uz + d0), e0 = ldw(un + d0);
        float4 a1 = ldw(ur + d1), b1 = ldw(uz + d1), e1 = ldw(un + d1);
        float4 p0 = ldx(h1 + d0), q0 = ldx(h2 + d0);
        float4 p1 = ldx(h1 + d1), q1 = ldx(h2 + d1);
        acc[6] += dot4(a0, p0); acc[7]  += dot4(b0, p0); acc[8]  += dot4(e0, p0);
        acc[9] += dot4(a0, q0); acc[10] += dot4(b0, q0); acc[11] += dot4(e0, q0);
        acc[6] += dot4(a1, p1); acc[7]  += dot4(b1, p1); acc[8]  += dot4(e1, p1);
        acc[9] += dot4(a1, q1); acc[10] += dot4(b1, q1); acc[11] += dot4(e1, q1);
    }
    if (c < nvh) {
        int d0 = c << 2;
        float4 a0 = ldw(ur + d0), b0 = ldw(uz + d0), e0 = ldw(un + d0);
        float4 p0 = ldx(h1 + d0), q0 = ldx(h2 + d0);
        acc[6] += dot4(a0, p0); acc[7]  += dot4(b0, p0); acc[8]  += dot4(e0, p0);
        acc[9] += dot4(a0, q0); acc[10] += dot4(b0, q0); acc[11] += dot4(e0, q0);
    }

    float s[12];
    blockReduce<12>(acc, s);
    if (threadIdx.x == 0) {
        float br = bih[j], bz = bih[H + j], bn = bih[2 * H + j];
        float cr = bhh[j], cz = bhh[H + j], cn = bhh[2 * H + j];
        {
            float r = sigm(s[0] + br + s[6] + cr);
            float z = sigm(s[1] + bz + s[7] + cz);
            float n = tanhf(s[2] + bn + r * (s[8] + cn));
            out1[j] = (1.0f - z) * n + z * h1[j];
        }
        {
            float r = sigm(s[3] + br + s[9] + cr);
            float z = sigm(s[4] + bz + s[10] + cz);
            float n = tanhf(s[5] + bn + r * (s[11] + cn));
            out2[j] = (1.0f - z) * n + z * h2[j];
        }
    }
}

// ---------------- K0: prep, one (copy,i) pair per thread ----------------
__global__ __launch_bounds__(NTHR) void k_prep(
    const float* __restrict__ x,
    const float* __restrict__ h1s, const float* __restrict__ h2s,
    const float* __restrict__ k1s, const float* __restrict__ k2s,
    const float* __restrict__ f1s, const float* __restrict__ f2s)
{
    int idx = blockIdx.x * blockDim.x + threadIdx.x;   // [0, 4*OSC)
    int h = idx >> 11;
    int i = idx & (OSC - 1);
    if (idx == 0) {
#pragma unroll
        for (int c = 0; c < 4; c++) {
            int o = cls_off(c);
            g_xm [c * XM_P + o + 0] = x[0];
            g_xm [c * XM_P + o + 1] = x[1];
            g_xm [c * XM_P + o + 2] = x[8];
            g_xm [c * XM_P + o + 3] = x[9];
            g_xm [c * XM_P + o + 4] = x[10];
            g_xk1[c * XK_P + o] = x[3]; g_xk2[c * XK_P + o] = x[6];
            g_xf1[c * XF_P + o] = x[4]; g_xf2[c * XF_P + o] = x[7];
        }
        g_hx[0] = x[2];
        g_hx[1] = x[5];
    }
    {
        float h1v = h1s[i], h2v = h2s[i], f1v = f1s[i], f2v = f2s[i];
        float k1v = k1s[i], k2v = k2s[i];
        int o = cls_off(h);
        g_xm [h * XM_P + o + 5 + i]        = h1v;
        g_xm [h * XM_P + o + 5 + OSC + i]  = h2v;
        g_xk1[h * XK_P + o + 1 + i]        = h1v;
        g_xk1[h * XK_P + o + 1 + OSC + i]  = f1v;
        g_xk2[h * XK_P + o + 1 + i]        = h2v;
        g_xk2[h * XK_P + o + 1 + OSC + i]  = f2v;
        g_xf1[h * XF_P + o + 1 + i]        = f1v;
        g_xf2[h * XF_P + o + 1 + i]        = f2v;
        g_sk1[h * SH_P + h + i] = k1v;
        g_sk2[h * SH_P + h + i] = k2v;
    }
}

// ---------------- K1: m + k + f + h_ind (all input-only; no sync) ----------------
// blocks: [0,4096) m | [4096,6144) k | [6144,8192) f | [8192,10240) h_ind
__global__ __launch_bounds__(NTHR) void k_main(
    const float* __restrict__ m_s,
    const float* __restrict__ h1s, const float* __restrict__ h2s,
    const float* __restrict__ k1s, const float* __restrict__ k2s,
    const float* __restrict__ f1s, const float* __restrict__ f2s,
    const float* __restrict__ m_wih, const float* __restrict__ m_whh,
    const float* __restrict__ m_bih, const float* __restrict__ m_bhh,
    const float* __restrict__ h_wih, const float* __restrict__ h_whh,
    const float* __restrict__ k_wih, const float* __restrict__ k_whh,
    const float* __restrict__ k_bih, const float* __restrict__ k_bhh,
    const float* __restrict__ f_wih, const float* __restrict__ f_whh,
    const float* __restrict__ f_bih, const float* __restrict__ f_bhh)
{
    const int b = blockIdx.x;
    const int tid = threadIdx.x;

    if (b < 4096) {
        gru_unit_single(m_wih, m_whh, m_bih, m_bhh, g_xm, XM_P, 5 + 2 * OSC,
                        m_s, MH, b, g_mnew);
    } else if (b < 6144) {
        gru_unit_dual(k_wih, k_whh, k_bih, k_bhh, g_xk1, g_xk2, XK_P, 1 + 2 * OSC,
                      k1s, k2s, OSC, b - 4096, g_k1new, g_k2new);
    } else if (b < 8192) {
        gru_unit_dual(f_wih, f_whh, f_bih, f_bhh, g_xf1, g_xf2, XF_P, 1 + OSC,
                      f1s, f2s, OSC, b - 6144, g_f1new, g_f2new);
    } else {
        // ---- h_ind: whh + wih col0 + wih cols [2049,4097) -> partials ----
        const int j = b - 8192;
        const int a = (j + 1) & 3;
        const int head = (4 - a) & 3;
        float acc[12] = {0,0,0,0,0,0,0,0,0,0,0,0};

        // whh (aligned): 512 vec cols, 2 per thread
        {
            const float* ur = h_whh + (size_t)j * OSC;
            const float* uz = ur + (size_t)OSC * OSC;
            const float* un = uz + (size_t)OSC * OSC;
            int d0 = tid << 2, d1 = d0 + 1024;
            float4 u0 = ldw(ur + d0), u1 = ldw(uz + d0), u2 = ldw(un + d0);
            float4 u3 = ldw(ur + d1), u4 = ldw(uz + d1), u5 = ldw(un + d1);
            float4 p0 = ldx(h1s + d0), p1 = ldx(h1s + d1);
            float4 q0 = ldx(h2s + d0), q1 = ldx(h2s + d1);
            acc[6] = dot4(u0, p0) + dot4(u3, p1);
            acc[7] = dot4(u1, p0) + dot4(u4, p1);
            acc[8] = dot4(u2, p0) + dot4(u5, p1);
            acc[9]  = dot4(u0, q0) + dot4(u3, q1);
            acc[10] = dot4(u1, q0) + dot4(u4, q1);
            acc[11] = dot4(u2, q0) + dot4(u5, q1);
        }
        // wih independent segment [2049, 4097): x = k1_s/k2_s
        {
            const float* wr = h_wih + (size_t)j * 4097 + 2049;
            const float* wz = wr + (size_t)OSC * 4097;
            const float* wn = wz + (size_t)OSC * 4097;
            const float* xk1 = g_sk1 + a * SH_P + a;
            const float* xk2 = g_sk2 + a * SH_P + a;
            const int nv = (2048 - head) >> 2;
            int e0 = head + (tid << 2);
            float4 w0 = ldw(wr + e0), w1 = ldw(wz + e0), w2 = ldw(wn + e0);
            float4 xp = ldx(xk1 + e0), xq = ldx(xk2 + e0);
            acc[0] += dot4(w0, xp); acc[1] += dot4(w1, xp); acc[2] += dot4(w2, xp);
            acc[3] += dot4(w0, xq); acc[4] += dot4(w1, xq); acc[5] += dot4(w2, xq);
            if (tid + NTHR < nv) {
                int e1 = head + ((tid + NTHR) << 2);
                float4 w3 = ldw(wr + e1), w4 = ldw(wz + e1), w5 = ldw(wn + e1);
                float4 xp1 = ldx(xk1 + e1), xq1 = ldx(xk2 + e1);
                acc[0] += dot4(w3, xp1); acc[1] += dot4(w4, xp1); acc[2] += dot4(w5, xp1);
                acc[3] += dot4(w3, xq1); acc[4] += dot4(w4, xq1); acc[5] += dot4(w5, xq1);
            }
            if (tid < head) {
                float xa = xk1[tid], xb = xk2[tid];
                float s0 = wr[tid], s1 = wz[tid], s2 = wn[tid];
                acc[0] += s0 * xa; acc[1] += s1 * xa; acc[2] += s2 * xa;
                acc[3] += s0 * xb; acc[4] += s1 * xb; acc[5] += s2 * xb;
            }
            const int tstart = head + (nv << 2);
            const int tcount = 2048 - tstart;
            if (tid >= 32 && tid - 32 < tcount) {
                int t = tstart + (tid - 32);
                float xa = xk1[t], xb = xk2[t];
                float s0 = wr[t], s1 = wz[t], s2 = wn[t];
                acc[0] += s0 * xa; acc[1] += s1 * xa; acc[2] += s2 * xa;
                acc[3] += s0 * xb; acc[4] += s1 * xb; acc[5] += s2 * xb;
            }
            if (tid == 64) {
                // wih col 0 (x = h observation scalars)
                const float* w0p = h_wih + (size_t)j * 4097;
                float w0 = w0p[0];
                float w1 = w0p[(size_t)OSC * 4097];
                float w2 = w0p[(size_t)2 * OSC * 4097];
                float hx1 = g_hx[0], hx2 = g_hx[1];
                acc[0] += w0 * hx1; acc[1] += w1 * hx1; acc[2] += w2 * hx1;
                acc[3] += w0 * hx2; acc[4] += w1 * hx2; acc[5] += w2 * hx2;
            }
        }
        float s[12];
        blockReduce<12>(acc, s);
        if (tid == 0) {
#pragma unroll
            for (int i = 0; i < 12; i++) g_hp[j][i] = s[i];
        }
    }
}

// ---------------- K2: mout rows + k/f heads (no internal deps) ----------------
// blocks: [0,4096) mout | [4096,4100) k/f heads
__global__ __launch_bounds__(NTHR) void k_mout(
    const float* __restrict__ w, const float* __restrict__ bias,
    const float* __restrict__ k_ow, const float* __restrict__ k_ob,
    const float* __restrict__ f_ow, const float* __restrict__ f_ob,
    float* __restrict__ out)
{
    const int b = blockIdx.x;
    const int tid = threadIdx.x;
    if (b < 4096) {
        const int r = b;
        const float* wr = w + (size_t)r * MH;
        int d0 = tid << 2;
        float4 a0 = ldw(wr + d0),        a1 = ldw(wr + d0 + 1024);
        float4 a2 = ldw(wr + d0 + 2048), a3 = ldw(wr + d0 + 3072);
        float4 m0 = ldx(g_mnew + d0),        m1 = ldx(g_mnew + d0 + 1024);
        float4 m2 = ldx(g_mnew + d0 + 2048), m3 = ldx(g_mnew + d0 + 3072);
        float acc[1];
        acc[0] = dot4(a0, m0) + dot4(a1, m1) + dot4(a2, m2) + dot4(a3, m3);
        float s[1];
        blockReduce<1>(acc, s);
        if (tid == 0) {
            float v = s[0] + bias[r];
            if (r < OSC) {
#pragma unroll
                for (int o = 0; o < 4; o++) g_so1[o * SH_P + o + r] = v;
            } else {
                int rr = r - OSC;
#pragma unroll
                for (int o = 0; o < 4; o++) g_so2[o * SH_P + o + rr] = v;
            }
        }
    } else {
        // k/f heads: k1->out[1], f1->out[2], k2->out[4], f2->out[5]
        const int hb = b - 4096;
        const float* vec;
        const float* hw;
        const float* bp;
        int oidx;
        switch (hb) {
            case 0:  vec = g_k1new; hw = k_ow; bp = k_ob; oidx = 1; break;
            case 1:  vec = g_f1new; hw = f_ow; bp = f_ob; oidx = 2; break;
            case 2:  vec = g_k2new; hw = k_ow; bp = k_ob; oidx = 4; break;
            default: vec = g_f2new; hw = f_ow; bp = f_ob; oidx = 5; break;
        }
        int d0 = tid << 2;
        float4 a0 = ldx(hw + d0), a1 = ldx(hw + d0 + 1024);
        float4 v0 = ldx(vec + d0), v1 = ldx(vec + d0 + 1024);
        float acc[1];
        acc[0] = dot4(a0, v0) + dot4(a1, v1);
        float s[1];
        blockReduce<1>(acc, s);
        if (tid == 0) out[oidx] = s[0] + bp[0];
    }
}

// ---------------- K3: h_dep, two units per block (j and j+1024, same class) ----------------
__global__ __launch_bounds__(NTHR) void k_hdep2(
    const float* __restrict__ h_wih,
    const float* __restrict__ h_bih, const float* __restrict__ h_bhh,
    const float* __restrict__ h1s, const float* __restrict__ h2s)
{
    const int j  = blockIdx.x;          // 0..1023
    const int j2 = j + 1024;
    const int tid = threadIdx.x;
    const int a = (j + 1) & 3;          // same class for j and j2
    const int head = (4 - a) & 3;
    const int nv = (2048 - head) >> 2;
    const float* wr = h_wih + (size_t)j * 4097 + 1;
    const float* wz = wr + (size_t)OSC * 4097;
    const float* wn = wz + (size_t)OSC * 4097;
    const float* vr = h_wih + (size_t)j2 * 4097 + 1;
    const float* vz = vr + (size_t)OSC * 4097;
    const float* vn = vz + (size_t)OSC * 4097;
    const float* xo1 = g_so1 + a * SH_P + a;
    const float* xo2 = g_so2 + a * SH_P + a;

    // acc[0..5] unit j (3 gates x 2 streams), acc[6..11] unit j2
    float acc[12] = {0,0,0,0,0,0,0,0,0,0,0,0};

    int e0 = head + (tid << 2);
    bool ok1 = (tid + NTHR < nv);
    int e1 = e0 + (NTHR << 2);

    // chunk 0: 6 weight loads + 2 shared x loads
    float4 w0 = ldw(wr + e0), w1 = ldw(wz + e0), w2 = ldw(wn + e0);
    float4 u0 = ldw(vr + e0), u1 = ldw(vz + e0), u2 = ldw(vn + e0);
    float4 p0 = ldx(xo1 + e0), q0 = ldx(xo2 + e0);
    // chunk 1 (guarded)
    float4 w3, w4, w5, u3, u4, u5, p1, q1;
    if (ok1) {
        w3 = ldw(wr + e1); w4 = ldw(wz + e1); w5 = ldw(wn + e1);
        u3 = ldw(vr + e1); u4 = ldw(vz + e1); u5 = ldw(vn + e1);
        p1 = ldx(xo1 + e1); q1 = ldx(xo2 + e1);
    }

    acc[0] += dot4(w0, p0); acc[1] += dot4(w1, p0); acc[2] += dot4(w2, p0);
    acc[3] += dot4(w0, q0); acc[4] += dot4(w1, q0); acc[5] += dot4(w2, q0);
    acc[6] += dot4(u0, p0); acc[7] += dot4(u1, p0); acc[8] += dot4(u2, p0);
    acc[9] += dot4(u0, q0); acc[10] += dot4(u1, q0); acc[11] += dot4(u2, q0);
    if (ok1) {
        acc[0] += dot4(w3, p1); acc[1] += dot4(w4, p1); acc[2] += dot4(w5, p1);
        acc[3] += dot4(w3, q1); acc[4] += dot4(w4, q1); acc[5] += dot4(w5, q1);
        acc[6] += dot4(u3, p1); acc[7] += dot4(u4, p1); acc[8] += dot4(u5, p1);
        acc[9] += dot4(u3, q1); acc[10] += dot4(u4, q1); acc[11] += dot4(u5, q1);
    }

    // head scalars [0, head)
    if (tid < head) {
        float xa = xo1[tid], xb = xo2[tid];
        float s0 = wr[tid], s1 = wz[tid], s2 = wn[tid];
        float t0 = vr[tid], t1 = vz[tid], t2 = vn[tid];
        acc[0] += s0 * xa; acc[1] += s1 * xa; acc[2] += s2 * xa;
        acc[3] += s0 * xb; acc[4] += s1 * xb; acc[5] += s2 * xb;
        acc[6] += t0 * xa; acc[7] += t1 * xa; acc[8] += t2 * xa;
        acc[9] += t0 * xb; acc[10] += t1 * xb; acc[11] += t2 * xb;
    }
    // tail scalars
    {
        const int tstart = head + (nv << 2);
        const int tcount = 2048 - tstart;
        if (tid >= 32 && tid - 32 < tcount) {
            int t = tstart + (tid - 32);
            float xa = xo1[t], xb = xo2[t];
            float s0 = wr[t], s1 = wz[t], s2 = wn[t];
            float t0 = vr[t], t1 = vz[t], t2 = vn[t];
            acc[0] += s0 * xa; acc[1] += s1 * xa; acc[2] += s2 * xa;
            acc[3] += s0 * xb; acc[4] += s1 * xb; acc[5] += s2 * xb;
            acc[6] += t0 * xa; acc[7] += t1 * xa; acc[8] += t2 * xa;
            acc[9] += t0 * xb; acc[10] += t1 * xb; acc[11] += t2 * xb;
        }
    }

    float s[12];
    blockReduce<12>(acc, s);
    if (tid == 0) {
#pragma unroll
        for (int u = 0; u < 2; u++) {
            const int jj = (u == 0) ? j : j2;
            const float* sv = s + 6 * u;
            float p[12];
#pragma unroll
            for (int i = 0; i < 12; i++) p[i] = g_hp[jj][i];
            float br = h_bih[jj], bz = h_bih[OSC + jj], bn = h_bih[2 * OSC + jj];
            float cr = h_bhh[jj], cz = h_bhh[OSC + jj], cn = h_bhh[2 * OSC + jj];
            {
                float r = sigm(p[0] + sv[0] + br + p[6] + cr);
                float z = sigm(p[1] + sv[1] + bz + p[7] + cz);
                float n = tanhf(p[2] + sv[2] + bn + r * (p[8] + cn));
                g_h1new[jj] = (1.0f - z) * n + z * h1s[jj];
            }
            {
                float r = sigm(p[3] + sv[3] + br + p[9] + cr);
                float z = sigm(p[4] + sv[4] + bz + p[10] + cz);
                float n = tanhf(p[5] + sv[5] + bn + r * (p[11] + cn));
                g_h2new[jj] = (1.0f - z) * n + z * h2s[jj];
            }
        }
    }
}

// ---------------- K4: two h output dot products ----------------
__global__ __launch_bounds__(NTHR) void k_heads_h(
    const float* __restrict__ h_ow, const float* __restrict__ h_ob,
    float* __restrict__ out)
{
    const int b = blockIdx.x;   // 0 -> h1 (out[0]), 1 -> h2 (out[3])
    const float* vec = (b == 0) ? g_h1new : g_h2new;
    int d0 = threadIdx.x << 2;
    float4 a0 = ldx(h_ow + d0), a1 = ldx(h_ow + d0 + 1024);
    float4 v0 = ldx(vec + d0), v1 = ldx(vec + d0 + 1024);
    float acc[1];
    acc[0] = dot4(a0, v0) + dot4(a1, v1);
    float s[1];
    blockReduce<1>(acc, s);
    if (threadIdx.x == 0) out[(b == 0) ? 0 : 3] = s[0] + h_ob[0];
}

// ---------------- launch ----------------
extern "C" void kernel_launch(void* const* d_in, const int* in_sizes, int n_in,
                              void* d_out, int out_size)
{
    const float* x      = (const float*)d_in[0];
    const float* m_s    = (const float*)d_in[1];
    const float* h1_s   = (const float*)d_in[2];
    const float* h2_s   = (const float*)d_in[3];
    const float* k1_s   = (const float*)d_in[4];
    const float* k2_s   = (const float*)d_in[5];
    const float* f1_s   = (const float*)d_in[6];
    const float* f2_s   = (const float*)d_in[7];
    const float* m_wih  = (const float*)d_in[8];
    const float* m_whh  = (const float*)d_in[9];
    const float* m_bih  = (const float*)d_in[10];
    const float* m_bhh  = (const float*)d_in[11];
    const float* m_ow   = (const float*)d_in[12];
    const float* m_ob   = (const float*)d_in[13];
    const float* h_wih  = (const float*)d_in[14];
    const float* h_whh  = (const float*)d_in[15];
    const float* h_bih  = (const float*)d_in[16];
    const float* h_bhh  = (const float*)d_in[17];
    const float* h_ow   = (const float*)d_in[18];
    const float* h_ob   = (const float*)d_in[19];
    const float* k_wih  = (const float*)d_in[20];
    const float* k_whh  = (const float*)d_in[21];
    const float* k_bih  = (const float*)d_in[22];
    const float* k_bhh  = (const float*)d_in[23];
    const float* k_ow   = (const float*)d_in[24];
    const float* k_ob   = (const float*)d_in[25];
    const float* f_wih  = (const float*)d_in[26];
    const float* f_whh  = (const float*)d_in[27];
    const float* f_bih  = (const float*)d_in[28];
    const float* f_bhh  = (const float*)d_in[29];
    const float* f_ow   = (const float*)d_in[30];
    const float* f_ob   = (const float*)d_in[31];
    float* out = (float*)d_out;

    k_prep<<<(4 * OSC) / NTHR, NTHR>>>(x, h1_s, h2_s, k1_s, k2_s, f1_s, f2_s);
    k_main<<<10240, NTHR>>>(m_s, h1_s, h2_s, k1_s, k2_s, f1_s, f2_s,
                            m_wih, m_whh, m_bih, m_bhh,
                            h_wih, h_whh,
                            k_wih, k_whh, k_bih, k_bhh,
                            f_wih, f_whh, f_bih, f_bhh);
    k_mout<<<4100, NTHR>>>(m_ow, m_ob, k_ow, k_ob, f_ow, f_ob, out);
    k_hdep2<<<1024, NTHR>>>(h_wih, h_bih, h_bhh, h1_s, h2_s);
    k_heads_h<<<2, NTHR>>>(h_ow, h_ob, out);
}

// round 10
// speedup vs baseline: 1.0428x; 1.0173x over previous
#include <cuda_runtime.h>

#define OSC 2048
#define MH  4096
#define NTHR 256

#define XM_P  4104
#define XK_P  4100
#define XF_P  2052
#define SH_P  2052   // shifted 2048-vectors (k-state, out_m halves)

// ---------------- scratch (no allocs allowed) ----------------
__device__ __align__(16) float g_xm [4 * XM_P];
__device__ __align__(16) float g_xk1[4 * XK_P], g_xk2[4 * XK_P];
__device__ __align__(16) float g_xf1[4 * XF_P], g_xf2[4 * XF_P];
__device__ __align__(16) float g_sk1[4 * SH_P], g_sk2[4 * SH_P];  // k1_s/k2_s shifted
__device__ __align__(16) float g_so1[4 * SH_P], g_so2[4 * SH_P];  // out_m halves shifted
__device__ __align__(16) float g_mnew[MH];
__device__ __align__(16) float g_h1new[OSC], g_h2new[OSC];
__device__ __align__(16) float g_k1new[OSC], g_k2new[OSC];
__device__ __align__(16) float g_f1new[OSC], g_f2new[OSC];
__device__ __align__(16) float g_hp[OSC][12];  // h_ind partials: [gi1(3), gi2(3), gh1(3), gh2(3)]
__device__ __align__(16) float g_hq[OSC][12];  // h_dep partials: [half0: s1(3) s2(3) | half1: s1(3) s2(3)]
__device__ float g_hx[2];                       // x[2], x[5]

__device__ __forceinline__ float sigm(float v) { return 1.0f / (1.0f + __expf(-v)); }
__device__ __forceinline__ int cls_off(int h) { return (4 - h) & 3; }

__device__ __forceinline__ float4 ldw(const float* p) {
    return __ldcs(reinterpret_cast<const float4*>(p));
}
__device__ __forceinline__ float4 ldx(const float* p) {
    return *reinterpret_cast<const float4*>(p);
}
__device__ __forceinline__ float dot4(float4 a, float4 b) {
    return a.x * b.x + a.y * b.y + a.z * b.z + a.w * b.w;
}

template <int NS>
__device__ __forceinline__ void blockReduce(float (&acc)[NS], float (&out)[NS]) {
    __shared__ float sm[NS][NTHR / 32];
    const int lane = threadIdx.x & 31;
    const int wid  = threadIdx.x >> 5;
#pragma unroll
    for (int s = 0; s < NS; s++) {
        float v = acc[s];
        v += __shfl_down_sync(0xffffffffu, v, 16);
        v += __shfl_down_sync(0xffffffffu, v, 8);
        v += __shfl_down_sync(0xffffffffu, v, 4);
        v += __shfl_down_sync(0xffffffffu, v, 2);
        v += __shfl_down_sync(0xffffffffu, v, 1);
        if (lane == 0) sm[s][wid] = v;
    }
    __syncthreads();
    if (threadIdx.x == 0) {
#pragma unroll
        for (int s = 0; s < NS; s++) {
            float v = 0.0f;
#pragma unroll
            for (int w = 0; w < NTHR / 32; w++) v += sm[s][w];
            out[s] = v;
        }
    }
}

// -------- single-stream GRU unit (m cell) --------
__device__ __forceinline__ void gru_unit_single(
    const float* __restrict__ wih, const float* __restrict__ whh,
    const float* __restrict__ bih, const float* __restrict__ bhh,
    const float* __restrict__ xbufs, int pad, int D,
    const float* __restrict__ hprev, int H, int j,
    float* __restrict__ newout)
{
    float acc[6] = {0, 0, 0, 0, 0, 0};
    const int head = (4 - (j & 3)) & 3;
    const float* xc = xbufs + head * pad + cls_off(head);
    const float* wr = wih + (size_t)j * D;
    const float* wz = wih + (size_t)(H + j) * D;
    const float* wn = wih + (size_t)(2 * H + j) * D;
    const int nvec = (D - head) >> 2;
    const int tail = D - head - (nvec << 2);

    if (threadIdx.x < (unsigned)head) {
        int d = threadIdx.x;
        float xv = xc[d];
        acc[0] += wr[d] * xv; acc[1] += wz[d] * xv; acc[2] += wn[d] * xv;
    }
    int c = threadIdx.x;
    for (; c + NTHR < nvec; c += 2 * NTHR) {
        int d0 = head + (c << 2);
        int d1 = d0 + (NTHR << 2);
        float4 a0 = ldw(wr + d0), b0 = ldw(wz + d0), e0 = ldw(wn + d0);
        float4 a1 = ldw(wr + d1), b1 = ldw(wz + d1), e1 = ldw(wn + d1);
        float4 x0 = ldx(xc + d0), x1 = ldx(xc + d1);
        acc[0] += dot4(a0, x0); acc[1] += dot4(b0, x0); acc[2] += dot4(e0, x0);
        acc[0] += dot4(a1, x1); acc[1] += dot4(b1, x1); acc[2] += dot4(e1, x1);
    }
    if (c < nvec) {
        int d0 = head + (c << 2);
        float4 a0 = ldw(wr + d0), b0 = ldw(wz + d0), e0 = ldw(wn + d0);
        float4 x0 = ldx(xc + d0);
        acc[0] += dot4(a0, x0); acc[1] += dot4(b0, x0); acc[2] += dot4(e0, x0);
    }
    if (threadIdx.x < (unsigned)tail) {
        int d = head + (nvec << 2) + threadIdx.x;
        float xv = xc[d];
        acc[0] += wr[d] * xv; acc[1] += wz[d] * xv; acc[2] += wn[d] * xv;
    }

    const float* ur = whh + (size_t)j * H;
    const float* uz = whh + (size_t)(H + j) * H;
    const float* un = whh + (size_t)(2 * H + j) * H;
    const int nvh = H >> 2;
    c = threadIdx.x;
    for (; c + NTHR < nvh; c += 2 * NTHR) {
        int d0 = c << 2, d1 = d0 + (NTHR << 2);
        float4 a0 = ldw(ur + d0), b0 = ldw(uz + d0), e0 = ldw(un + d0);
        float4 a1 = ldw(ur + d1), b1 = ldw(uz + d1), e1 = ldw(un + d1);
        float4 h0 = ldx(hprev + d0), h1v = ldx(hprev + d1);
        acc[3] += dot4(a0, h0); acc[4] += dot4(b0, h0); acc[5] += dot4(e0, h0);
        acc[3] += dot4(a1, h1v); acc[4] += dot4(b1, h1v); acc[5] += dot4(e1, h1v);
    }
    if (c < nvh) {
        int d0 = c << 2;
        float4 a0 = ldw(ur + d0), b0 = ldw(uz + d0), e0 = ldw(un + d0);
        float4 h0 = ldx(hprev + d0);
        acc[3] += dot4(a0, h0); acc[4] += dot4(b0, h0); acc[5] += dot4(e0, h0);
    }

    float s[6];
    blockReduce<6>(acc, s);
    if (threadIdx.x == 0) {
        float r = sigm(s[0] + bih[j] + s[3] + bhh[j]);
        float z = sigm(s[1] + bih[H + j] + s[4] + bhh[H + j]);
        float n = tanhf(s[2] + bih[2 * H + j] + r * (s[5] + bhh[2 * H + j]));
        newout[j] = (1.0f - z) * n + z * hprev[j];
    }
}

// -------- dual-stream GRU unit (k/f cells) --------
__device__ __forceinline__ void gru_unit_dual(
    const float* __restrict__ wih, const float* __restrict__ whh,
    const float* __restrict__ bih, const float* __restrict__ bhh,
    const float* __restrict__ x1bufs, const float* __restrict__ x2bufs, int pad, int D,
    const float* __restrict__ h1, const float* __restrict__ h2, int H, int j,
    float* __restrict__ out1, float* __restrict__ out2)
{
    float acc[12] = {0, 0, 0, 0, 0, 0, 0, 0, 0, 0, 0, 0};
    const int head = (4 - (j & 3)) & 3;
    const int off  = head * pad + cls_off(head);
    const float* x1c = x1bufs + off;
    const float* x2c = x2bufs + off;
    const float* wr = wih + (size_t)j * D;
    const float* wz = wih + (size_t)(H + j) * D;
    const float* wn = wih + (size_t)(2 * H + j) * D;
    const int nvec = (D - head) >> 2;
    const int tail = D - head - (nvec << 2);

    if (threadIdx.x < (unsigned)head) {
        int d = threadIdx.x;
        float a = x1c[d], b = x2c[d];
        float w0 = wr[d], w1 = wz[d], w2 = wn[d];
        acc[0] += w0 * a; acc[1] += w1 * a; acc[2] += w2 * a;
        acc[3] += w0 * b; acc[4] += w1 * b; acc[5] += w2 * b;
    }
    int c = threadIdx.x;
    for (; c + NTHR < nvec; c += 2 * NTHR) {
        int d0 = head + (c << 2), d1 = d0 + (NTHR << 2);
        float4 a0 = ldw(wr + d0), b0 = ldw(wz + d0), e0 = ldw(wn + d0);
        float4 a1 = ldw(wr + d1), b1 = ldw(wz + d1), e1 = ldw(wn + d1);
        float4 p0 = ldx(x1c + d0), q0 = ldx(x2c + d0);
        float4 p1 = ldx(x1c + d1), q1 = ldx(x2c + d1);
        acc[0] += dot4(a0, p0); acc[1] += dot4(b0, p0); acc[2] += dot4(e0, p0);
        acc[3] += dot4(a0, q0); acc[4] += dot4(b0, q0); acc[5] += dot4(e0, q0);
        acc[0] += dot4(a1, p1); acc[1] += dot4(b1, p1); acc[2] += dot4(e1, p1);
        acc[3] += dot4(a1, q1); acc[4] += dot4(b1, q1); acc[5] += dot4(e1, q1);
    }
    if (c < nvec) {
        int d0 = head + (c << 2);
        float4 a0 = ldw(wr + d0), b0 = ldw(wz + d0), e0 = ldw(wn + d0);
        float4 p0 = ldx(x1c + d0), q0 = ldx(x2c + d0);
        acc[0] += dot4(a0, p0); acc[1] += dot4(b0, p0); acc[2] += dot4(e0, p0);
        acc[3] += dot4(a0, q0); acc[4] += dot4(b0, q0); acc[5] += dot4(e0, q0);
    }
    if (threadIdx.x < (unsigned)tail) {
        int d = head + (nvec << 2) + threadIdx.x;
        float a = x1c[d], b = x2c[d];
        float w0 = wr[d], w1 = wz[d], w2 = wn[d];
        acc[0] += w0 * a; acc[1] += w1 * a; acc[2] += w2 * a;
        acc[3] += w0 * b; acc[4] += w1 * b; acc[5] += w2 * b;
    }

    const float* ur = whh + (size_t)j * H;
    const float* uz = whh + (size_t)(H + j) * H;
    const float* un = whh + (size_t)(2 * H + j) * H;
    const int nvh = H >> 2;
    c = threadIdx.x;
    for (; c + NTHR < nvh; c += 2 * NTHR) {
        int d0 = c << 2, d1 = d0 + (NTHR << 2);
        float4 a0 = ldw(ur + d0), b0 = ldw(uz + d0), e0 = ldw(un + d0);
        float4 a1 = ldw(ur + d1), b1 = ldw(uz + d1), e1 = ldw(un + d1);
        float4 p0 = ldx(h1 + d0), q0 = ldx(h2 + d0);
        float4 p1 = ldx(h1 + d1), q1 = ldx(h2 + d1);
        acc[6] += dot4(a0, p0); acc[7]  += dot4(b0, p0); acc[8]  += dot4(e0, p0);
        acc[9] += dot4(a0, q0); acc[10] += dot4(b0, q0); acc[11] += dot4(e0, q0);
        acc[6] += dot4(a1, p1); acc[7]  += dot4(b1, p1); acc[8]  += dot4(e1, p1);
        acc[9] += dot4(a1, q1); acc[10] += dot4(b1, q1); acc[11] += dot4(e1, q1);
    }
    if (c < nvh) {
        int d0 = c << 2;
        float4 a0 = ldw(ur + d0), b0 = ldw(uz + d0), e0 = ldw(un + d0);
        float4 p0 = ldx(h1 + d0), q0 = ldx(h2 + d0);
        acc[6] += dot4(a0, p0); acc[7]  += dot4(b0, p0); acc[8]  += dot4(e0, p0);
        acc[9] += dot4(a0, q0); acc[10] += dot4(b0, q0); acc[11] += dot4(e0, q0);
    }

    float s[12];
    blockReduce<12>(acc, s);
    if (threadIdx.x == 0) {
        float br = bih[j], bz = bih[H + j], bn = bih[2 * H + j];
        float cr = bhh[j], cz = bhh[H + j], cn = bhh[2 * H + j];
        {
            float r = sigm(s[0] + br + s[6] + cr);
            float z = sigm(s[1] + bz + s[7] + cz);
            float n = tanhf(s[2] + bn + r * (s[8] + cn));
            out1[j] = (1.0f - z) * n + z * h1[j];
        }
        {
            float r = sigm(s[3] + br + s[9] + cr);
            float z = sigm(s[4] + bz + s[10] + cz);
            float n = tanhf(s[5] + bn + r * (s[11] + cn));
            out2[j] = (1.0f - z) * n + z * h2[j];
        }
    }
}

// ---------------- K0: prep ----------------
__global__ __launch_bounds__(NTHR) void k_prep(
    const float* __restrict__ x,
    const float* __restrict__ h1s, const float* __restrict__ h2s,
    const float* __restrict__ k1s, const float* __restrict__ k2s,
    const float* __restrict__ f1s, const float* __restrict__ f2s)
{
    int idx = blockIdx.x * blockDim.x + threadIdx.x;   // [0, 4*OSC)
    int h = idx >> 11;
    int i = idx & (OSC - 1);
    if (idx == 0) {
#pragma unroll
        for (int c = 0; c < 4; c++) {
            int o = cls_off(c);
            g_xm [c * XM_P + o + 0] = x[0];
            g_xm [c * XM_P + o + 1] = x[1];
            g_xm [c * XM_P + o + 2] = x[8];
            g_xm [c * XM_P + o + 3] = x[9];
            g_xm [c * XM_P + o + 4] = x[10];
            g_xk1[c * XK_P + o] = x[3]; g_xk2[c * XK_P + o] = x[6];
            g_xf1[c * XF_P + o] = x[4]; g_xf2[c * XF_P + o] = x[7];
        }
        g_hx[0] = x[2];
        g_hx[1] = x[5];
    }
    {
        float h1v = h1s[i], h2v = h2s[i], f1v = f1s[i], f2v = f2s[i];
        float k1v = k1s[i], k2v = k2s[i];
        int o = cls_off(h);
        g_xm [h * XM_P + o + 5 + i]        = h1v;
        g_xm [h * XM_P + o + 5 + OSC + i]  = h2v;
        g_xk1[h * XK_P + o + 1 + i]        = h1v;
        g_xk1[h * XK_P + o + 1 + OSC + i]  = f1v;
        g_xk2[h * XK_P + o + 1 + i]        = h2v;
        g_xk2[h * XK_P + o + 1 + OSC + i]  = f2v;
        g_xf1[h * XF_P + o + 1 + i]        = f1v;
        g_xf2[h * XF_P + o + 1 + i]        = f2v;
        g_sk1[h * SH_P + h + i] = k1v;
        g_sk2[h * SH_P + h + i] = k2v;
    }
}

// ---------------- K1: m + k + f + h_ind (all input-only; no sync) ----------------
__global__ __launch_bounds__(NTHR) void k_main(
    const float* __restrict__ m_s,
    const float* __restrict__ h1s, const float* __restrict__ h2s,
    const float* __restrict__ k1s, const float* __restrict__ k2s,
    const float* __restrict__ f1s, const float* __restrict__ f2s,
    const float* __restrict__ m_wih, const float* __restrict__ m_whh,
    const float* __restrict__ m_bih, const float* __restrict__ m_bhh,
    const float* __restrict__ h_wih, const float* __restrict__ h_whh,
    const float* __restrict__ k_wih, const float* __restrict__ k_whh,
    const float* __restrict__ k_bih, const float* __restrict__ k_bhh,
    const float* __restrict__ f_wih, const float* __restrict__ f_whh,
    const float* __restrict__ f_bih, const float* __restrict__ f_bhh)
{
    const int b = blockIdx.x;
    const int tid = threadIdx.x;

    if (b < 4096) {
        gru_unit_single(m_wih, m_whh, m_bih, m_bhh, g_xm, XM_P, 5 + 2 * OSC,
                        m_s, MH, b, g_mnew);
    } else if (b < 6144) {
        gru_unit_dual(k_wih, k_whh, k_bih, k_bhh, g_xk1, g_xk2, XK_P, 1 + 2 * OSC,
                      k1s, k2s, OSC, b - 4096, g_k1new, g_k2new);
    } else if (b < 8192) {
        gru_unit_dual(f_wih, f_whh, f_bih, f_bhh, g_xf1, g_xf2, XF_P, 1 + OSC,
                      f1s, f2s, OSC, b - 6144, g_f1new, g_f2new);
    } else {
        // ---- h_ind: whh + wih col0 + wih cols [2049,4097) -> partials ----
        const int j = b - 8192;
        const int a = (j + 1) & 3;
        const int head = (4 - a) & 3;
        float acc[12] = {0,0,0,0,0,0,0,0,0,0,0,0};

        {
            const float* ur = h_whh + (size_t)j * OSC;
            const float* uz = ur + (size_t)OSC * OSC;
            const float* un = uz + (size_t)OSC * OSC;
            int d0 = tid << 2, d1 = d0 + 1024;
            float4 u0 = ldw(ur + d0), u1 = ldw(uz + d0), u2 = ldw(un + d0);
            float4 u3 = ldw(ur + d1), u4 = ldw(uz + d1), u5 = ldw(un + d1);
            float4 p0 = ldx(h1s + d0), p1 = ldx(h1s + d1);
            float4 q0 = ldx(h2s + d0), q1 = ldx(h2s + d1);
            acc[6] = dot4(u0, p0) + dot4(u3, p1);
            acc[7] = dot4(u1, p0) + dot4(u4, p1);
            acc[8] = dot4(u2, p0) + dot4(u5, p1);
            acc[9]  = dot4(u0, q0) + dot4(u3, q1);
            acc[10] = dot4(u1, q0) + dot4(u4, q1);
            acc[11] = dot4(u2, q0) + dot4(u5, q1);
        }
        {
            const float* wr = h_wih + (size_t)j * 4097 + 2049;
            const float* wz = wr + (size_t)OSC * 4097;
            const float* wn = wz + (size_t)OSC * 4097;
            const float* xk1 = g_sk1 + a * SH_P + a;
            const float* xk2 = g_sk2 + a * SH_P + a;
            const int nv = (2048 - head) >> 2;
            int e0 = head + (tid << 2);
            float4 w0 = ldw(wr + e0), w1 = ldw(wz + e0), w2 = ldw(wn + e0);
            float4 xp = ldx(xk1 + e0), xq = ldx(xk2 + e0);
            acc[0] += dot4(w0, xp); acc[1] += dot4(w1, xp); acc[2] += dot4(w2, xp);
            acc[3] += dot4(w0, xq); acc[4] += dot4(w1, xq); acc[5] += dot4(w2, xq);
            if (tid + NTHR < nv) {
                int e1 = head + ((tid + NTHR) << 2);
                float4 w3 = ldw(wr + e1), w4 = ldw(wz + e1), w5 = ldw(wn + e1);
                float4 xp1 = ldx(xk1 + e1), xq1 = ldx(xk2 + e1);
                acc[0] += dot4(w3, xp1); acc[1] += dot4(w4, xp1); acc[2] += dot4(w5, xp1);
                acc[3] += dot4(w3, xq1); acc[4] += dot4(w4, xq1); acc[5] += dot4(w5, xq1);
            }
            if (tid < head) {
                float xa = xk1[tid], xb = xk2[tid];
                float s0 = wr[tid], s1 = wz[tid], s2 = wn[tid];
                acc[0] += s0 * xa; acc[1] += s1 * xa; acc[2] += s2 * xa;
                acc[3] += s0 * xb; acc[4] += s1 * xb; acc[5] += s2 * xb;
            }
            const int tstart = head + (nv << 2);
            const int tcount = 2048 - tstart;
            if (tid >= 32 && tid - 32 < tcount) {
                int t = tstart + (tid - 32);
                float xa = xk1[t], xb = xk2[t];
                float s0 = wr[t], s1 = wz[t], s2 = wn[t];
                acc[0] += s0 * xa; acc[1] += s1 * xa; acc[2] += s2 * xa;
                acc[3] += s0 * xb; acc[4] += s1 * xb; acc[5] += s2 * xb;
            }
            if (tid == 64) {
                const float* w0p = h_wih + (size_t)j * 4097;
                float w0 = w0p[0];
                float w1 = w0p[(size_t)OSC * 4097];
                float w2 = w0p[(size_t)2 * OSC * 4097];
                float hx1 = g_hx[0], hx2 = g_hx[1];
                acc[0] += w0 * hx1; acc[1] += w1 * hx1; acc[2] += w2 * hx1;
                acc[3] += w0 * hx2; acc[4] += w1 * hx2; acc[5] += w2 * hx2;
            }
        }
        float s[12];
        blockReduce<12>(acc, s);
        if (tid == 0) {
#pragma unroll
            for (int i = 0; i < 12; i++) g_hp[j][i] = s[i];
        }
    }
}

// ---------------- K2: mout rows + k/f heads (no internal deps) ----------------
__global__ __launch_bounds__(NTHR) void k_mout(
    const float* __restrict__ w, const float* __restrict__ bias,
    const float* __restrict__ k_ow, const float* __restrict__ k_ob,
    const float* __restrict__ f_ow, const float* __restrict__ f_ob,
    float* __restrict__ out)
{
    const int b = blockIdx.x;
    const int tid = threadIdx.x;
    if (b < 4096) {
        const int r = b;
        const float* wr = w + (size_t)r * MH;
        int d0 = tid << 2;
        float4 a0 = ldw(wr + d0),        a1 = ldw(wr + d0 + 1024);
        float4 a2 = ldw(wr + d0 + 2048), a3 = ldw(wr + d0 + 3072);
        float4 m0 = ldx(g_mnew + d0),        m1 = ldx(g_mnew + d0 + 1024);
        float4 m2 = ldx(g_mnew + d0 + 2048), m3 = ldx(g_mnew + d0 + 3072);
        float acc[1];
        acc[0] = dot4(a0, m0) + dot4(a1, m1) + dot4(a2, m2) + dot4(a3, m3);
        float s[1];
        blockReduce<1>(acc, s);
        if (tid == 0) {
            float v = s[0] + bias[r];
            if (r < OSC) {
#pragma unroll
                for (int o = 0; o < 4; o++) g_so1[o * SH_P + o + r] = v;
            } else {
                int rr = r - OSC;
#pragma unroll
                for (int o = 0; o < 4; o++) g_so2[o * SH_P + o + rr] = v;
            }
        }
    } else {
        const int hb = b - 4096;
        const float* vec;
        const float* hw;
        const float* bp;
        int oidx;
        switch (hb) {
            case 0:  vec = g_k1new; hw = k_ow; bp = k_ob; oidx = 1; break;
            case 1:  vec = g_f1new; hw = f_ow; bp = f_ob; oidx = 2; break;
            case 2:  vec = g_k2new; hw = k_ow; bp = k_ob; oidx = 4; break;
            default: vec = g_f2new; hw = f_ow; bp = f_ob; oidx = 5; break;
        }
        int d0 = tid << 2;
        float4 a0 = ldx(hw + d0), a1 = ldx(hw + d0 + 1024);
        float4 v0 = ldx(vec + d0), v1 = ldx(vec + d0 + 1024);
        float acc[1];
        acc[0] = dot4(a0, v0) + dot4(a1, v1);
        float s[1];
        blockReduce<1>(acc, s);
        if (tid == 0) out[oidx] = s[0] + bp[0];
    }
}

// ---------------- K3: h_dep partials — mout-shaped: 4096 light blocks ----------------
// block b: unit j = b & 2047, column-half = b >> 11. Writes 6 single-writer partials.
__global__ __launch_bounds__(NTHR) void k_hdepP(
    const float* __restrict__ h_wih)
{
    const int b = blockIdx.x;
    const int j = b & (OSC - 1);
    const int half = b >> 11;
    const int tid = threadIdx.x;
    const int a = (j + 1) & 3;
    const int head = (4 - a) & 3;
    const float* wr = h_wih + (size_t)j * 4097 + 1;
    const float* wz = wr + (size_t)OSC * 4097;
    const float* wn = wz + (size_t)OSC * 4097;
    const float* xo1 = g_so1 + a * SH_P + a;
    const float* xo2 = g_so2 + a * SH_P + a;

    float acc[6] = {0, 0, 0, 0, 0, 0};

    if (half == 0) {
        // float4 chunks 0..255 (always valid: nv >= 511) + head scalars
        int e0 = head + (tid << 2);
        float4 w0 = ldw(wr + e0), w1 = ldw(wz + e0), w2 = ldw(wn + e0);
        float4 p0 = ldx(xo1 + e0), q0 = ldx(xo2 + e0);
        acc[0] = dot4(w0, p0); acc[1] = dot4(w1, p0); acc[2] = dot4(w2, p0);
        acc[3] = dot4(w0, q0); acc[4] = dot4(w1, q0); acc[5] = dot4(w2, q0);
        if (tid < head) {
            float xa = xo1[tid], xb = xo2[tid];
            float s0 = wr[tid], s1 = wz[tid], s2 = wn[tid];
            acc[0] += s0 * xa; acc[1] += s1 * xa; acc[2] += s2 * xa;
            acc[3] += s0 * xb; acc[4] += s1 * xb; acc[5] += s2 * xb;
        }
    } else {
        // float4 chunks 256..nv-1 + tail scalars
        const int nv = (2048 - head) >> 2;   // 511 or 512
        int c = 256 + tid;
        if (c < nv) {
            int e0 = head + (c << 2);
            float4 w0 = ldw(wr + e0), w1 = ldw(wz + e0), w2 = ldw(wn + e0);
            float4 p0 = ldx(xo1 + e0), q0 = ldx(xo2 + e0);
            acc[0] = dot4(w0, p0); acc[1] = dot4(w1, p0); acc[2] = dot4(w2, p0);
            acc[3] = dot4(w0, q0); acc[4] = dot4(w1, q0); acc[5] = dot4(w2, q0);
        }
        const int tstart = head + (nv << 2);
        const int tcount = 2048 - tstart;    // 0..3
        if (tid >= 32 && tid - 32 < tcount) {
            int t = tstart + (tid - 32);
            float xa = xo1[t], xb = xo2[t];
            float s0 = wr[t], s1 = wz[t], s2 = wn[t];
            acc[0] += s0 * xa; acc[1] += s1 * xa; acc[2] += s2 * xa;
            acc[3] += s0 * xb; acc[4] += s1 * xb; acc[5] += s2 * xb;
        }
    }

    float s[6];
    blockReduce<6>(acc, s);
    if (tid == 0) {
#pragma unroll
        for (int i = 0; i < 6; i++) g_hq[j][6 * half + i] = s[i];
    }
}

// ---------------- K4: gate epilogue, one thread per h-unit ----------------
__global__ __launch_bounds__(NTHR) void k_gates(
    const float* __restrict__ h_bih, const float* __restrict__ h_bhh,
    const float* __restrict__ h1s, const float* __restrict__ h2s)
{
    const int j = blockIdx.x * NTHR + threadIdx.x;   // 8 blocks -> 2048
    // load all partials as float4 (both arrays 16B aligned, 12 floats = 3 float4)
    const float4* hp4 = reinterpret_cast<const float4*>(g_hp[j]);
    const float4* hq4 = reinterpret_cast<const float4*>(g_hq[j]);
    float4 pa = hp4[0], pb = hp4[1], pc = hp4[2];
    float4 qa = hq4[0], qb = hq4[1], qc = hq4[2];
    // hp: [gi1 r z n | gi2 r z n | gh1 r z n | gh2 r z n]
    // hq: [dep1 half0 r z n | dep2 half0 r z n | dep1 half1 r z n | dep2 half1 r z n]
    float gi1r = pa.x + qa.x + qb.z;
    float gi1z = pa.y + qa.y + qb.w;
    float gi1n = pa.z + qa.z + qc.x;
    float gi2r = pa.w + qa.w + qc.y;
    float gi2z = pb.x + qb.x + qc.z;
    float gi2n = pb.y + qb.y + qc.w;
    float gh1r = pb.z, gh1z = pb.w, gh1n = pc.x;
    float gh2r = pc.y, gh2z = pc.z, gh2n = pc.w;
    float br = h_bih[j], bz = h_bih[OSC + j], bn = h_bih[2 * OSC + j];
    float cr = h_bhh[j], cz = h_bhh[OSC + j], cn = h_bhh[2 * OSC + j];
    {
        float r = sigm(gi1r + br + gh1r + cr);
        float z = sigm(gi1z + bz + gh1z + cz);
        float n = tanhf(gi1n + bn + r * (gh1n + cn));
        g_h1new[j] = (1.0f - z) * n + z * h1s[j];
    }
    {
        float r = sigm(gi2r + br + gh2r + cr);
        float z = sigm(gi2z + bz + gh2z + cz);
        float n = tanhf(gi2n + bn + r * (gh2n + cn));
        g_h2new[j] = (1.0f - z) * n + z * h2s[j];
    }
}

// ---------------- K5: two h output dot products ----------------
__global__ __launch_bounds__(NTHR) void k_heads_h(
    const float* __restrict__ h_ow, const float* __restrict__ h_ob,
    float* __restrict__ out)
{
    const int b = blockIdx.x;   // 0 -> h1 (out[0]), 1 -> h2 (out[3])
    const float* vec = (b == 0) ? g_h1new : g_h2new;
    int d0 = threadIdx.x << 2;
    float4 a0 = ldx(h_ow + d0), a1 = ldx(h_ow + d0 + 1024);
    float4 v0 = ldx(vec + d0), v1 = ldx(vec + d0 + 1024);
    float acc[1];
    acc[0] = dot4(a0, v0) + dot4(a1, v1);
    float s[1];
    blockReduce<1>(acc, s);
    if (threadIdx.x == 0) out[(b == 0) ? 0 : 3] = s[0] + h_ob[0];
}

// ---------------- launch ----------------
extern "C" void kernel_launch(void* const* d_in, const int* in_sizes, int n_in,
                              void* d_out, int out_size)
{
    const float* x      = (const float*)d_in[0];
    const float* m_s    = (const float*)d_in[1];
    const float* h1_s   = (const float*)d_in[2];
    const float* h2_s   = (const float*)d_in[3];
    const float* k1_s   = (const float*)d_in[4];
    const float* k2_s   = (const float*)d_in[5];
    const float* f1_s   = (const float*)d_in[6];
    const float* f2_s   = (const float*)d_in[7];
    const float* m_wih  = (const float*)d_in[8];
    const float* m_whh  = (const float*)d_in[9];
    const float* m_bih  = (const float*)d_in[10];
    const float* m_bhh  = (const float*)d_in[11];
    const float* m_ow   = (const float*)d_in[12];
    const float* m_ob   = (const float*)d_in[13];
    const float* h_wih  = (const float*)d_in[14];
    const float* h_whh  = (const float*)d_in[15];
    const float* h_bih  = (const float*)d_in[16];
    const float* h_bhh  = (const float*)d_in[17];
    const float* h_ow   = (const float*)d_in[18];
    const float* h_ob   = (const float*)d_in[19];
    const float* k_wih  = (const float*)d_in[20];
    const float* k_whh  = (const float*)d_in[21];
    const float* k_bih  = (const float*)d_in[22];
    const float* k_bhh  = (const float*)d_in[23];
    const float* k_ow   = (const float*)d_in[24];
    const float* k_ob   = (const float*)d_in[25];
    const float* f_wih  = (const float*)d_in[26];
    const float* f_whh  = (const float*)d_in[27];
    const float* f_bih  = (const float*)d_in[28];
    const float* f_bhh  = (const float*)d_in[29];
    const float* f_ow   = (const float*)d_in[30];
    const float* f_ob   = (const float*)d_in[31];
    float* out = (float*)d_out;

    k_prep<<<(4 * OSC) / NTHR, NTHR>>>(x, h1_s, h2_s, k1_s, k2_s, f1_s, f2_s);
    k_main<<<10240, NTHR>>>(m_s, h1_s, h2_s, k1_s, k2_s, f1_s, f2_s,
                            m_wih, m_whh, m_bih, m_bhh,
                            h_wih, h_whh,
                            k_wih, k_whh, k_bih, k_bhh,
                            f_wih, f_whh, f_bih, f_bhh);
    k_mout<<<4100, NTHR>>>(m_ow, m_ob, k_ow, k_ob, f_ow, f_ob, out);
    k_hdepP<<<2 * OSC, NTHR>>>(h_wih);
    k_gates<<<OSC / NTHR, NTHR>>>(h_bih, h_bhh, h1_s, h2_s);
    k_heads_h<<<2, NTHR>>>(h_ow, h_ob, out);
}

// round 11
// speedup vs baseline: 1.0675x; 1.0237x over previous
#include <cuda_runtime.h>

#define OSC 2048
#define MH  4096
#define NTHR 256

#define XM_P  4104
#define XK_P  4100
#define XF_P  2052
#define SH_P  2052   // shifted 2048-vectors (k-state, out_m halves)

// ---------------- scratch (no allocs allowed) ----------------
__device__ __align__(16) float g_xm [4 * XM_P];
__device__ __align__(16) float g_xk1[4 * XK_P], g_xk2[4 * XK_P];
__device__ __align__(16) float g_xf1[4 * XF_P], g_xf2[4 * XF_P];
__device__ __align__(16) float g_sk1[4 * SH_P], g_sk2[4 * SH_P];  // k1_s/k2_s shifted
__device__ __align__(16) float g_so1[4 * SH_P], g_so2[4 * SH_P];  // out_m halves shifted
__device__ __align__(16) float g_mnew[MH];
__device__ __align__(16) float g_h1new[OSC], g_h2new[OSC];
__device__ __align__(16) float g_k1new[OSC], g_k2new[OSC];
__device__ __align__(16) float g_f1new[OSC], g_f2new[OSC];
__device__ __align__(16) float g_hp[OSC][12];  // h_ind partials: [gi1(3), gi2(3), gh1(3), gh2(3)]
__device__ __align__(32) float g_hq[OSC][8];   // h_dep partials: [gate g, stream s] at 2g+s
__device__ float g_hx[2];                       // x[2], x[5]

__device__ __forceinline__ float sigm(float v) { return 1.0f / (1.0f + __expf(-v)); }
__device__ __forceinline__ int cls_off(int h) { return (4 - h) & 3; }

__device__ __forceinline__ float4 ldw(const float* p) {
    return __ldcs(reinterpret_cast<const float4*>(p));
}
__device__ __forceinline__ float4 ldx(const float* p) {
    return *reinterpret_cast<const float4*>(p);
}
__device__ __forceinline__ float dot4(float4 a, float4 b) {
    return a.x * b.x + a.y * b.y + a.z * b.z + a.w * b.w;
}

template <int NS>
__device__ __forceinline__ void blockReduce(float (&acc)[NS], float (&out)[NS]) {
    __shared__ float sm[NS][NTHR / 32];
    const int lane = threadIdx.x & 31;
    const int wid  = threadIdx.x >> 5;
#pragma unroll
    for (int s = 0; s < NS; s++) {
        float v = acc[s];
        v += __shfl_down_sync(0xffffffffu, v, 16);
        v += __shfl_down_sync(0xffffffffu, v, 8);
        v += __shfl_down_sync(0xffffffffu, v, 4);
        v += __shfl_down_sync(0xffffffffu, v, 2);
        v += __shfl_down_sync(0xffffffffu, v, 1);
        if (lane == 0) sm[s][wid] = v;
    }
    __syncthreads();
    if (threadIdx.x == 0) {
#pragma unroll
        for (int s = 0; s < NS; s++) {
            float v = 0.0f;
#pragma unroll
            for (int w = 0; w < NTHR / 32; w++) v += sm[s][w];
            out[s] = v;
        }
    }
}

// -------- single-stream GRU unit (m cell) --------
__device__ __forceinline__ void gru_unit_single(
    const float* __restrict__ wih, const float* __restrict__ whh,
    const float* __restrict__ bih, const float* __restrict__ bhh,
    const float* __restrict__ xbufs, int pad, int D,
    const float* __restrict__ hprev, int H, int j,
    float* __restrict__ newout)
{
    float acc[6] = {0, 0, 0, 0, 0, 0};
    const int head = (4 - (j & 3)) & 3;
    const float* xc = xbufs + head * pad + cls_off(head);
    const float* wr = wih + (size_t)j * D;
    const float* wz = wih + (size_t)(H + j) * D;
    const float* wn = wih + (size_t)(2 * H + j) * D;
    const int nvec = (D - head) >> 2;
    const int tail = D - head - (nvec << 2);

    if (threadIdx.x < (unsigned)head) {
        int d = threadIdx.x;
        float xv = xc[d];
        acc[0] += wr[d] * xv; acc[1] += wz[d] * xv; acc[2] += wn[d] * xv;
    }
    int c = threadIdx.x;
    for (; c + NTHR < nvec; c += 2 * NTHR) {
        int d0 = head + (c << 2);
        int d1 = d0 + (NTHR << 2);
        float4 a0 = ldw(wr + d0), b0 = ldw(wz + d0), e0 = ldw(wn + d0);
        float4 a1 = ldw(wr + d1), b1 = ldw(wz + d1), e1 = ldw(wn + d1);
        float4 x0 = ldx(xc + d0), x1 = ldx(xc + d1);
        acc[0] += dot4(a0, x0); acc[1] += dot4(b0, x0); acc[2] += dot4(e0, x0);
        acc[0] += dot4(a1, x1); acc[1] += dot4(b1, x1); acc[2] += dot4(e1, x1);
    }
    if (c < nvec) {
        int d0 = head + (c << 2);
        float4 a0 = ldw(wr + d0), b0 = ldw(wz + d0), e0 = ldw(wn + d0);
        float4 x0 = ldx(xc + d0);
        acc[0] += dot4(a0, x0); acc[1] += dot4(b0, x0); acc[2] += dot4(e0, x0);
    }
    if (threadIdx.x < (unsigned)tail) {
        int d = head + (nvec << 2) + threadIdx.x;
        float xv = xc[d];
        acc[0] += wr[d] * xv; acc[1] += wz[d] * xv; acc[2] += wn[d] * xv;
    }

    const float* ur = whh + (size_t)j * H;
    const float* uz = whh + (size_t)(H + j) * H;
    const float* un = whh + (size_t)(2 * H + j) * H;
    const int nvh = H >> 2;
    c = threadIdx.x;
    for (; c + NTHR < nvh; c += 2 * NTHR) {
        int d0 = c << 2, d1 = d0 + (NTHR << 2);
        float4 a0 = ldw(ur + d0), b0 = ldw(uz + d0), e0 = ldw(un + d0);
        float4 a1 = ldw(ur + d1), b1 = ldw(uz + d1), e1 = ldw(un + d1);
        float4 h0 = ldx(hprev + d0), h1v = ldx(hprev + d1);
        acc[3] += dot4(a0, h0); acc[4] += dot4(b0, h0); acc[5] += dot4(e0, h0);
        acc[3] += dot4(a1, h1v); acc[4] += dot4(b1, h1v); acc[5] += dot4(e1, h1v);
    }
    if (c < nvh) {
        int d0 = c << 2;
        float4 a0 = ldw(ur + d0), b0 = ldw(uz + d0), e0 = ldw(un + d0);
        float4 h0 = ldx(hprev + d0);
        acc[3] += dot4(a0, h0); acc[4] += dot4(b0, h0); acc[5] += dot4(e0, h0);
    }

    float s[6];
    blockReduce<6>(acc, s);
    if (threadIdx.x == 0) {
        float r = sigm(s[0] + bih[j] + s[3] + bhh[j]);
        float z = sigm(s[1] + bih[H + j] + s[4] + bhh[H + j]);
        float n = tanhf(s[2] + bih[2 * H + j] + r * (s[5] + bhh[2 * H + j]));
        newout[j] = (1.0f - z) * n + z * hprev[j];
    }
}

// -------- dual-stream GRU unit (k/f cells) --------
__device__ __forceinline__ void gru_unit_dual(
    const float* __restrict__ wih, const float* __restrict__ whh,
    const float* __restrict__ bih, const float* __restrict__ bhh,
    const float* __restrict__ x1bufs, const float* __restrict__ x2bufs, int pad, int D,
    const float* __restrict__ h1, const float* __restrict__ h2, int H, int j,
    float* __restrict__ out1, float* __restrict__ out2)
{
    float acc[12] = {0, 0, 0, 0, 0, 0, 0, 0, 0, 0, 0, 0};
    const int head = (4 - (j & 3)) & 3;
    const int off  = head * pad + cls_off(head);
    const float* x1c = x1bufs + off;
    const float* x2c = x2bufs + off;
    const float* wr = wih + (size_t)j * D;
    const float* wz = wih + (size_t)(H + j) * D;
    const float* wn = wih + (size_t)(2 * H + j) * D;
    const int nvec = (D - head) >> 2;
    const int tail = D - head - (nvec << 2);

    if (threadIdx.x < (unsigned)head) {
        int d = threadIdx.x;
        float a = x1c[d], b = x2c[d];
        float w0 = wr[d], w1 = wz[d], w2 = wn[d];
        acc[0] += w0 * a; acc[1] += w1 * a; acc[2] += w2 * a;
        acc[3] += w0 * b; acc[4] += w1 * b; acc[5] += w2 * b;
    }
    int c = threadIdx.x;
    for (; c + NTHR < nvec; c += 2 * NTHR) {
        int d0 = head + (c << 2), d1 = d0 + (NTHR << 2);
        float4 a0 = ldw(wr + d0), b0 = ldw(wz + d0), e0 = ldw(wn + d0);
        float4 a1 = ldw(wr + d1), b1 = ldw(wz + d1), e1 = ldw(wn + d1);
        float4 p0 = ldx(x1c + d0), q0 = ldx(x2c + d0);
        float4 p1 = ldx(x1c + d1), q1 = ldx(x2c + d1);
        acc[0] += dot4(a0, p0); acc[1] += dot4(b0, p0); acc[2] += dot4(e0, p0);
        acc[3] += dot4(a0, q0); acc[4] += dot4(b0, q0); acc[5] += dot4(e0, q0);
        acc[0] += dot4(a1, p1); acc[1] += dot4(b1, p1); acc[2] += dot4(e1, p1);
        acc[3] += dot4(a1, q1); acc[4] += dot4(b1, q1); acc[5] += dot4(e1, q1);
    }
    if (c < nvec) {
        int d0 = head + (c << 2);
        float4 a0 = ldw(wr + d0), b0 = ldw(wz + d0), e0 = ldw(wn + d0);
        float4 p0 = ldx(x1c + d0), q0 = ldx(x2c + d0);
        acc[0] += dot4(a0, p0); acc[1] += dot4(b0, p0); acc[2] += dot4(e0, p0);
        acc[3] += dot4(a0, q0); acc[4] += dot4(b0, q0); acc[5] += dot4(e0, q0);
    }
    if (threadIdx.x < (unsigned)tail) {
        int d = head + (nvec << 2) + threadIdx.x;
        float a = x1c[d], b = x2c[d];
        float w0 = wr[d], w1 = wz[d], w2 = wn[d];
        acc[0] += w0 * a; acc[1] += w1 * a; acc[2] += w2 * a;
        acc[3] += w0 * b; acc[4] += w1 * b; acc[5] += w2 * b;
    }

    const float* ur = whh + (size_t)j * H;
    const float* uz = whh + (size_t)(H + j) * H;
    const float* un = whh + (size_t)(2 * H + j) * H;
    const int nvh = H >> 2;
    c = threadIdx.x;
    for (; c + NTHR < nvh; c += 2 * NTHR) {
        int d0 = c << 2, d1 = d0 + (NTHR << 2);
        float4 a0 = ldw(ur + d0), b0 = ldw(uz + d0), e0 = ldw(un + d0);
        float4 a1 = ldw(ur + d1), b1 = ldw(uz + d1), e1 = ldw(un + d1);
        float4 p0 = ldx(h1 + d0), q0 = ldx(h2 + d0);
        float4 p1 = ldx(h1 + d1), q1 = ldx(h2 + d1);
        acc[6] += dot4(a0, p0); acc[7]  += dot4(b0, p0); acc[8]  += dot4(e0, p0);
        acc[9] += dot4(a0, q0); acc[10] += dot4(b0, q0); acc[11] += dot4(e0, q0);
        acc[6] += dot4(a1, p1); acc[7]  += dot4(b1, p1); acc[8]  += dot4(e1, p1);
        acc[9] += dot4(a1, q1); acc[10] += dot4(b1, q1); acc[11] += dot4(e1, q1);
    }
    if (c < nvh) {
        int d0 = c << 2;
        float4 a0 = ldw(ur + d0), b0 = ldw(uz + d0), e0 = ldw(un + d0);
        float4 p0 = ldx(h1 + d0), q0 = ldx(h2 + d0);
        acc[6] += dot4(a0, p0); acc[7]  += dot4(b0, p0); acc[8]  += dot4(e0, p0);
        acc[9] += dot4(a0, q0); acc[10] += dot4(b0, q0); acc[11] += dot4(e0, q0);
    }

    float s[12];
    blockReduce<12>(acc, s);
    if (threadIdx.x == 0) {
        float br = bih[j], bz = bih[H + j], bn = bih[2 * H + j];
        float cr = bhh[j], cz = bhh[H + j], cn = bhh[2 * H + j];
        {
            float r = sigm(s[0] + br + s[6] + cr);
            float z = sigm(s[1] + bz + s[7] + cz);
            float n = tanhf(s[2] + bn + r * (s[8] + cn));
            out1[j] = (1.0f - z) * n + z * h1[j];
        }
        {
            float r = sigm(s[3] + br + s[9] + cr);
            float z = sigm(s[4] + bz + s[10] + cz);
            float n = tanhf(s[5] + bn + r * (s[11] + cn));
            out2[j] = (1.0f - z) * n + z * h2[j];
        }
    }
}

// ---------------- K0: prep ----------------
__global__ __launch_bounds__(NTHR) void k_prep(
    const float* __restrict__ x,
    const float* __restrict__ h1s, const float* __restrict__ h2s,
    const float* __restrict__ k1s, const float* __restrict__ k2s,
    const float* __restrict__ f1s, const float* __restrict__ f2s)
{
    int idx = blockIdx.x * blockDim.x + threadIdx.x;   // [0, 4*OSC)
    int h = idx >> 11;
    int i = idx & (OSC - 1);
    // scalar slots: 4 threads, one copy each (parallel instead of serial chain)
    if (blockIdx.x == 0 && threadIdx.x < 4) {
        int c = threadIdx.x;
        int o = cls_off(c);
        g_xm [c * XM_P + o + 0] = x[0];
        g_xm [c * XM_P + o + 1] = x[1];
        g_xm [c * XM_P + o + 2] = x[8];
        g_xm [c * XM_P + o + 3] = x[9];
        g_xm [c * XM_P + o + 4] = x[10];
        g_xk1[c * XK_P + o] = x[3]; g_xk2[c * XK_P + o] = x[6];
        g_xf1[c * XF_P + o] = x[4]; g_xf2[c * XF_P + o] = x[7];
        if (c == 0) { g_hx[0] = x[2]; g_hx[1] = x[5]; }
    }
    {
        float h1v = h1s[i], h2v = h2s[i], f1v = f1s[i], f2v = f2s[i];
        float k1v = k1s[i], k2v = k2s[i];
        int o = cls_off(h);
        g_xm [h * XM_P + o + 5 + i]        = h1v;
        g_xm [h * XM_P + o + 5 + OSC + i]  = h2v;
        g_xk1[h * XK_P + o + 1 + i]        = h1v;
        g_xk1[h * XK_P + o + 1 + OSC + i]  = f1v;
        g_xk2[h * XK_P + o + 1 + i]        = h2v;
        g_xk2[h * XK_P + o + 1 + OSC + i]  = f2v;
        g_xf1[h * XF_P + o + 1 + i]        = f1v;
        g_xf2[h * XF_P + o + 1 + i]        = f2v;
        g_sk1[h * SH_P + h + i] = k1v;
        g_sk2[h * SH_P + h + i] = k2v;
    }
}

// ---------------- K1: m + k + f + h_ind (all input-only; no sync) ----------------
__global__ __launch_bounds__(NTHR) void k_main(
    const float* __restrict__ m_s,
    const float* __restrict__ h1s, const float* __restrict__ h2s,
    const float* __restrict__ k1s, const float* __restrict__ k2s,
    const float* __restrict__ f1s, const float* __restrict__ f2s,
    const float* __restrict__ m_wih, const float* __restrict__ m_whh,
    const float* __restrict__ m_bih, const float* __restrict__ m_bhh,
    const float* __restrict__ h_wih, const float* __restrict__ h_whh,
    const float* __restrict__ k_wih, const float* __restrict__ k_whh,
    const float* __restrict__ k_bih, const float* __restrict__ k_bhh,
    const float* __restrict__ f_wih, const float* __restrict__ f_whh,
    const float* __restrict__ f_bih, const float* __restrict__ f_bhh)
{
    const int b = blockIdx.x;
    const int tid = threadIdx.x;

    if (b < 4096) {
        gru_unit_single(m_wih, m_whh, m_bih, m_bhh, g_xm, XM_P, 5 + 2 * OSC,
                        m_s, MH, b, g_mnew);
    } else if (b < 6144) {
        gru_unit_dual(k_wih, k_whh, k_bih, k_bhh, g_xk1, g_xk2, XK_P, 1 + 2 * OSC,
                      k1s, k2s, OSC, b - 4096, g_k1new, g_k2new);
    } else if (b < 8192) {
        gru_unit_dual(f_wih, f_whh, f_bih, f_bhh, g_xf1, g_xf2, XF_P, 1 + OSC,
                      f1s, f2s, OSC, b - 6144, g_f1new, g_f2new);
    } else {
        // ---- h_ind: whh + wih col0 + wih cols [2049,4097) -> partials ----
        const int j = b - 8192;
        const int a = (j + 1) & 3;
        const int head = (4 - a) & 3;
        float acc[12] = {0,0,0,0,0,0,0,0,0,0,0,0};

        {
            const float* ur = h_whh + (size_t)j * OSC;
            const float* uz = ur + (size_t)OSC * OSC;
            const float* un = uz + (size_t)OSC * OSC;
            int d0 = tid << 2, d1 = d0 + 1024;
            float4 u0 = ldw(ur + d0), u1 = ldw(uz + d0), u2 = ldw(un + d0);
            float4 u3 = ldw(ur + d1), u4 = ldw(uz + d1), u5 = ldw(un + d1);
            float4 p0 = ldx(h1s + d0), p1 = ldx(h1s + d1);
            float4 q0 = ldx(h2s + d0), q1 = ldx(h2s + d1);
            acc[6] = dot4(u0, p0) + dot4(u3, p1);
            acc[7] = dot4(u1, p0) + dot4(u4, p1);
            acc[8] = dot4(u2, p0) + dot4(u5, p1);
            acc[9]  = dot4(u0, q0) + dot4(u3, q1);
            acc[10] = dot4(u1, q0) + dot4(u4, q1);
            acc[11] = dot4(u2, q0) + dot4(u5, q1);
        }
        {
            const float* wr = h_wih + (size_t)j * 4097 + 2049;
            const float* wz = wr + (size_t)OSC * 4097;
            const float* wn = wz + (size_t)OSC * 4097;
            const float* xk1 = g_sk1 + a * SH_P + a;
            const float* xk2 = g_sk2 + a * SH_P + a;
            const int nv = (2048 - head) >> 2;
            int e0 = head + (tid << 2);
            float4 w0 = ldw(wr + e0), w1 = ldw(wz + e0), w2 = ldw(wn + e0);
            float4 xp = ldx(xk1 + e0), xq = ldx(xk2 + e0);
            acc[0] += dot4(w0, xp); acc[1] += dot4(w1, xp); acc[2] += dot4(w2, xp);
            acc[3] += dot4(w0, xq); acc[4] += dot4(w1, xq); acc[5] += dot4(w2, xq);
            if (tid + NTHR < nv) {
                int e1 = head + ((tid + NTHR) << 2);
                float4 w3 = ldw(wr + e1), w4 = ldw(wz + e1), w5 = ldw(wn + e1);
                float4 xp1 = ldx(xk1 + e1), xq1 = ldx(xk2 + e1);
                acc[0] += dot4(w3, xp1); acc[1] += dot4(w4, xp1); acc[2] += dot4(w5, xp1);
                acc[3] += dot4(w3, xq1); acc[4] += dot4(w4, xq1); acc[5] += dot4(w5, xq1);
            }
            if (tid < head) {
                float xa = xk1[tid], xb = xk2[tid];
                float s0 = wr[tid], s1 = wz[tid], s2 = wn[tid];
                acc[0] += s0 * xa; acc[1] += s1 * xa; acc[2] += s2 * xa;
                acc[3] += s0 * xb; acc[4] += s1 * xb; acc[5] += s2 * xb;
            }
            const int tstart = head + (nv << 2);
            const int tcount = 2048 - tstart;
            if (tid >= 32 && tid - 32 < tcount) {
                int t = tstart + (tid - 32);
                float xa = xk1[t], xb = xk2[t];
                float s0 = wr[t], s1 = wz[t], s2 = wn[t];
                acc[0] += s0 * xa; acc[1] += s1 * xa; acc[2] += s2 * xa;
                acc[3] += s0 * xb; acc[4] += s1 * xb; acc[5] += s2 * xb;
            }
            if (tid == 64) {
                const float* w0p = h_wih + (size_t)j * 4097;
                float w0 = w0p[0];
                float w1 = w0p[(size_t)OSC * 4097];
                float w2 = w0p[(size_t)2 * OSC * 4097];
                float hx1 = g_hx[0], hx2 = g_hx[1];
                acc[0] += w0 * hx1; acc[1] += w1 * hx1; acc[2] += w2 * hx1;
                acc[3] += w0 * hx2; acc[4] += w1 * hx2; acc[5] += w2 * hx2;
            }
        }
        float s[12];
        blockReduce<12>(acc, s);
        if (tid == 0) {
#pragma unroll
            for (int i = 0; i < 12; i++) g_hp[j][i] = s[i];
        }
    }
}

// ---------------- K2: mout rows + k/f heads (no internal deps) ----------------
__global__ __launch_bounds__(NTHR) void k_mout(
    const float* __restrict__ w, const float* __restrict__ bias,
    const float* __restrict__ k_ow, const float* __restrict__ k_ob,
    const float* __restrict__ f_ow, const float* __restrict__ f_ob,
    float* __restrict__ out)
{
    const int b = blockIdx.x;
    const int tid = threadIdx.x;
    if (b < 4096) {
        const int r = b;
        const float* wr = w + (size_t)r * MH;
        int d0 = tid << 2;
        float4 a0 = ldw(wr + d0),        a1 = ldw(wr + d0 + 1024);
        float4 a2 = ldw(wr + d0 + 2048), a3 = ldw(wr + d0 + 3072);
        float4 m0 = ldx(g_mnew + d0),        m1 = ldx(g_mnew + d0 + 1024);
        float4 m2 = ldx(g_mnew + d0 + 2048), m3 = ldx(g_mnew + d0 + 3072);
        float acc[1];
        acc[0] = dot4(a0, m0) + dot4(a1, m1) + dot4(a2, m2) + dot4(a3, m3);
        float s[1];
        blockReduce<1>(acc, s);
        if (tid == 0) {
            float v = s[0] + bias[r];
            if (r < OSC) {
#pragma unroll
                for (int o = 0; o < 4; o++) g_so1[o * SH_P + o + r] = v;
            } else {
                int rr = r - OSC;
#pragma unroll
                for (int o = 0; o < 4; o++) g_so2[o * SH_P + o + rr] = v;
            }
        }
    } else {
        const int hb = b - 4096;
        const float* vec;
        const float* hw;
        const float* bp;
        int oidx;
        switch (hb) {
            case 0:  vec = g_k1new; hw = k_ow; bp = k_ob; oidx = 1; break;
            case 1:  vec = g_f1new; hw = f_ow; bp = f_ob; oidx = 2; break;
            case 2:  vec = g_k2new; hw = k_ow; bp = k_ob; oidx = 4; break;
            default: vec = g_f2new; hw = f_ow; bp = f_ob; oidx = 5; break;
        }
        int d0 = tid << 2;
        float4 a0 = ldx(hw + d0), a1 = ldx(hw + d0 + 1024);
        float4 v0 = ldx(vec + d0), v1 = ldx(vec + d0 + 1024);
        float acc[1];
        acc[0] = dot4(a0, v0) + dot4(a1, v1);
        float s[1];
        blockReduce<1>(acc, s);
        if (tid == 0) out[oidx] = s[0] + bp[0];
    }
}

// ---------------- K3: h_dep partials — ONE gate row per block (contiguous 8 KB) ----------------
// block b: gate g = b >> 11, unit j = b & 2047. Both streams. Writes g_hq[j][2g+s].
__global__ __launch_bounds__(NTHR) void k_hdepG(
    const float* __restrict__ h_wih)
{
    const int b = blockIdx.x;
    const int g = b >> 11;
    const int j = b & (OSC - 1);
    const int tid = threadIdx.x;
    const int a = (j + 1) & 3;
    const int head = (4 - a) & 3;
    const float* wrow = h_wih + (size_t)(g * OSC + j) * 4097 + 1;
    const float* xo1 = g_so1 + a * SH_P + a;
    const float* xo2 = g_so2 + a * SH_P + a;
    const int nv = (2048 - head) >> 2;   // 511 or 512

    float acc[2] = {0, 0};
    int e0 = head + (tid << 2);
    // chunk 0 always valid (tid < 256 <= nv)
    float4 w0 = ldw(wrow + e0);
    float4 p0 = ldx(xo1 + e0), q0 = ldx(xo2 + e0);
    // chunk 1 guarded
    bool ok1 = (tid + NTHR < nv);
    int e1 = e0 + (NTHR << 2);
    if (ok1) {
        float4 w1 = ldw(wrow + e1);
        float4 p1 = ldx(xo1 + e1), q1 = ldx(xo2 + e1);
        acc[0] += dot4(w1, p1);
        acc[1] += dot4(w1, q1);
    }
    acc[0] += dot4(w0, p0);
    acc[1] += dot4(w0, q0);
    // head scalars
    if (tid < head) {
        float wv = wrow[tid];
        acc[0] += wv * xo1[tid];
        acc[1] += wv * xo2[tid];
    }
    // tail scalars
    {
        const int tstart = head + (nv << 2);
        const int tcount = 2048 - tstart;    // 0..3
        if (tid >= 32 && tid - 32 < tcount) {
            int t = tstart + (tid - 32);
            float wv = wrow[t];
            acc[0] += wv * xo1[t];
            acc[1] += wv * xo2[t];
        }
    }

    float s[2];
    blockReduce<2>(acc, s);
    if (tid == 0) {
        g_hq[j][2 * g]     = s[0];
        g_hq[j][2 * g + 1] = s[1];
    }
}

// ---------------- K4: gate epilogue, one thread per h-unit ----------------
__global__ __launch_bounds__(NTHR) void k_gates(
    const float* __restrict__ h_bih, const float* __restrict__ h_bhh,
    const float* __restrict__ h1s, const float* __restrict__ h2s)
{
    const int j = blockIdx.x * NTHR + threadIdx.x;   // 8 blocks -> 2048
    const float4* hp4 = reinterpret_cast<const float4*>(g_hp[j]);
    const float4* hq4 = reinterpret_cast<const float4*>(g_hq[j]);
    float4 pa = hp4[0], pb = hp4[1], pc = hp4[2];
    float4 qa = hq4[0], qb = hq4[1];
    // hp: [gi1 r z n | gi2 r z n | gh1 r z n | gh2 r z n]
    // hq: [r_s1 r_s2 z_s1 z_s2 n_s1 n_s2 _ _]  (index 2g+s)
    float gi1r = pa.x + qa.x;
    float gi1z = pa.y + qa.z;
    float gi1n = pa.z + qb.x;
    float gi2r = pa.w + qa.y;
    float gi2z = pb.x + qa.w;
    float gi2n = pb.y + qb.y;
    float gh1r = pb.z, gh1z = pb.w, gh1n = pc.x;
    float gh2r = pc.y, gh2z = pc.z, gh2n = pc.w;
    float br = h_bih[j], bz = h_bih[OSC + j], bn = h_bih[2 * OSC + j];
    float cr = h_bhh[j], cz = h_bhh[OSC + j], cn = h_bhh[2 * OSC + j];
    {
        float r = sigm(gi1r + br + gh1r + cr);
        float z = sigm(gi1z + bz + gh1z + cz);
        float n = tanhf(gi1n + bn + r * (gh1n + cn));
        g_h1new[j] = (1.0f - z) * n + z * h1s[j];
    }
    {
        float r = sigm(gi2r + br + gh2r + cr);
        float z = sigm(gi2z + bz + gh2z + cz);
        float n = tanhf(gi2n + bn + r * (gh2n + cn));
        g_h2new[j] = (1.0f - z) * n + z * h2s[j];
    }
}

// ---------------- K5: two h output dot products ----------------
__global__ __launch_bounds__(NTHR) void k_heads_h(
    const float* __restrict__ h_ow, const float* __restrict__ h_ob,
    float* __restrict__ out)
{
    const int b = blockIdx.x;   // 0 -> h1 (out[0]), 1 -> h2 (out[3])
    const float* vec = (b == 0) ? g_h1new : g_h2new;
    int d0 = threadIdx.x << 2;
    float4 a0 = ldx(h_ow + d0), a1 = ldx(h_ow + d0 + 1024);
    float4 v0 = ldx(vec + d0), v1 = ldx(vec + d0 + 1024);
    float acc[1];
    acc[0] = dot4(a0, v0) + dot4(a1, v1);
    float s[1];
    blockReduce<1>(acc, s);
    if (threadIdx.x == 0) out[(b == 0) ? 0 : 3] = s[0] + h_ob[0];
}

// ---------------- launch ----------------
extern "C" void kernel_launch(void* const* d_in, const int* in_sizes, int n_in,
                              void* d_out, int out_size)
{
    const float* x      = (const float*)d_in[0];
    const float* m_s    = (const float*)d_in[1];
    const float* h1_s   = (const float*)d_in[2];
    const float* h2_s   = (const float*)d_in[3];
    const float* k1_s   = (const float*)d_in[4];
    const float* k2_s   = (const float*)d_in[5];
    const float* f1_s   = (const float*)d_in[6];
    const float* f2_s   = (const float*)d_in[7];
    const float* m_wih  = (const float*)d_in[8];
    const float* m_whh  = (const float*)d_in[9];
    const float* m_bih  = (const float*)d_in[10];
    const float* m_bhh  = (const float*)d_in[11];
    const float* m_ow   = (const float*)d_in[12];
    const float* m_ob   = (const float*)d_in[13];
    const float* h_wih  = (const float*)d_in[14];
    const float* h_whh  = (const float*)d_in[15];
    const float* h_bih  = (const float*)d_in[16];
    const float* h_bhh  = (const float*)d_in[17];
    const float* h_ow   = (const float*)d_in[18];
    const float* h_ob   = (const float*)d_in[19];
    const float* k_wih  = (const float*)d_in[20];
    const float* k_whh  = (const float*)d_in[21];
    const float* k_bih  = (const float*)d_in[22];
    const float* k_bhh  = (const float*)d_in[23];
    const float* k_ow   = (const float*)d_in[24];
    const float* k_ob   = (const float*)d_in[25];
    const float* f_wih  = (const float*)d_in[26];
    const float* f_whh  = (const float*)d_in[27];
    const float* f_bih  = (const float*)d_in[28];
    const float* f_bhh  = (const float*)d_in[29];
    const float* f_ow   = (const float*)d_in[30];
    const float* f_ob   = (const float*)d_in[31];
    float* out = (float*)d_out;

    k_prep<<<(4 * OSC) / NTHR, NTHR>>>(x, h1_s, h2_s, k1_s, k2_s, f1_s, f2_s);
    k_main<<<10240, NTHR>>>(m_s, h1_s, h2_s, k1_s, k2_s, f1_s, f2_s,
                            m_wih, m_whh, m_bih, m_bhh,
                            h_wih, h_whh,
                            k_wih, k_whh, k_bih, k_bhh,
                            f_wih, f_whh, f_bih, f_bhh);
    k_mout<<<4100, NTHR>>>(m_ow, m_ob, k_ow, k_ob, f_ow, f_ob, out);
    k_hdepG<<<3 * OSC, NTHR>>>(h_wih);
    k_gates<<<OSC / NTHR, NTHR>>>(h_bih, h_bhh, h1_s, h2_s);
    k_heads_h<<<2, NTHR>>>(h_ow, h_ob, out);
}

// round 12
// speedup vs baseline: 1.0689x; 1.0013x over previous
#include <cuda_runtime.h>

#define OSC 2048
#define MH  4096
#define NTHR 256

#define XM_P  4104
#define XK_P  4100
#define XF_P  2052
#define SH_P  2052   // shifted 2048-vectors (k-state, out_m halves)

// ---------------- scratch (no allocs allowed) ----------------
__device__ __align__(16) float g_xm [4 * XM_P];
__device__ __align__(16) float g_xk1[4 * XK_P], g_xk2[4 * XK_P];
__device__ __align__(16) float g_xf1[4 * XF_P], g_xf2[4 * XF_P];
__device__ __align__(16) float g_sk1[4 * SH_P], g_sk2[4 * SH_P];  // k1_s/k2_s shifted
__device__ __align__(16) float g_so1[4 * SH_P], g_so2[4 * SH_P];  // out_m halves shifted
__device__ __align__(16) float g_mnew[MH];
__device__ __align__(16) float g_h1new[OSC], g_h2new[OSC];
__device__ __align__(16) float g_k1new[OSC], g_k2new[OSC];
__device__ __align__(16) float g_f1new[OSC], g_f2new[OSC];
__device__ __align__(16) float g_hp[OSC][12];  // h_ind partials: [gi1(3), gi2(3), gh1(3), gh2(3)]
__device__ __align__(32) float g_hq[OSC][8];   // h_dep partials: [gate g, stream s] at 2g+s
__device__ float g_hx[2];                       // x[2], x[5]

__device__ __forceinline__ float sigm(float v) { return 1.0f / (1.0f + __expf(-v)); }
__device__ __forceinline__ int cls_off(int h) { return (4 - h) & 3; }

__device__ __forceinline__ float4 ldw(const float* p) {
    return __ldcs(reinterpret_cast<const float4*>(p));
}
__device__ __forceinline__ float4 ldx(const float* p) {
    return *reinterpret_cast<const float4*>(p);
}
__device__ __forceinline__ float dot4(float4 a, float4 b) {
    return a.x * b.x + a.y * b.y + a.z * b.z + a.w * b.w;
}

template <int NS>
__device__ __forceinline__ void blockReduce(float (&acc)[NS], float (&out)[NS]) {
    __shared__ float sm[NS][NTHR / 32];
    const int lane = threadIdx.x & 31;
    const int wid  = threadIdx.x >> 5;
#pragma unroll
    for (int s = 0; s < NS; s++) {
        float v = acc[s];
        v += __shfl_down_sync(0xffffffffu, v, 16);
        v += __shfl_down_sync(0xffffffffu, v, 8);
        v += __shfl_down_sync(0xffffffffu, v, 4);
        v += __shfl_down_sync(0xffffffffu, v, 2);
        v += __shfl_down_sync(0xffffffffu, v, 1);
        if (lane == 0) sm[s][wid] = v;
    }
    __syncthreads();
    if (threadIdx.x == 0) {
#pragma unroll
        for (int s = 0; s < NS; s++) {
            float v = 0.0f;
#pragma unroll
            for (int w = 0; w < NTHR / 32; w++) v += sm[s][w];
            out[s] = v;
        }
    }
}

// -------- single-stream GRU unit (m cell) --------
__device__ __forceinline__ void gru_unit_single(
    const float* __restrict__ wih, const float* __restrict__ whh,
    const float* __restrict__ bih, const float* __restrict__ bhh,
    const float* __restrict__ xbufs, int pad, int D,
    const float* __restrict__ hprev, int H, int j,
    float* __restrict__ newout)
{
    float acc[6] = {0, 0, 0, 0, 0, 0};
    const int head = (4 - (j & 3)) & 3;
    const float* xc = xbufs + head * pad + cls_off(head);
    const float* wr = wih + (size_t)j * D;
    const float* wz = wih + (size_t)(H + j) * D;
    const float* wn = wih + (size_t)(2 * H + j) * D;
    const int nvec = (D - head) >> 2;
    const int tail = D - head - (nvec << 2);

    if (threadIdx.x < (unsigned)head) {
        int d = threadIdx.x;
        float xv = xc[d];
        acc[0] += wr[d] * xv; acc[1] += wz[d] * xv; acc[2] += wn[d] * xv;
    }
    int c = threadIdx.x;
    for (; c + NTHR < nvec; c += 2 * NTHR) {
        int d0 = head + (c << 2);
        int d1 = d0 + (NTHR << 2);
        float4 a0 = ldw(wr + d0), b0 = ldw(wz + d0), e0 = ldw(wn + d0);
        float4 a1 = ldw(wr + d1), b1 = ldw(wz + d1), e1 = ldw(wn + d1);
        float4 x0 = ldx(xc + d0), x1 = ldx(xc + d1);
        acc[0] += dot4(a0, x0); acc[1] += dot4(b0, x0); acc[2] += dot4(e0, x0);
        acc[0] += dot4(a1, x1); acc[1] += dot4(b1, x1); acc[2] += dot4(e1, x1);
    }
    if (c < nvec) {
        int d0 = head + (c << 2);
        float4 a0 = ldw(wr + d0), b0 = ldw(wz + d0), e0 = ldw(wn + d0);
        float4 x0 = ldx(xc + d0);
        acc[0] += dot4(a0, x0); acc[1] += dot4(b0, x0); acc[2] += dot4(e0, x0);
    }
    if (threadIdx.x < (unsigned)tail) {
        int d = head + (nvec << 2) + threadIdx.x;
        float xv = xc[d];
        acc[0] += wr[d] * xv; acc[1] += wz[d] * xv; acc[2] += wn[d] * xv;
    }

    const float* ur = whh + (size_t)j * H;
    const float* uz = whh + (size_t)(H + j) * H;
    const float* un = whh + (size_t)(2 * H + j) * H;
    const int nvh = H >> 2;
    c = threadIdx.x;
    for (; c + NTHR < nvh; c += 2 * NTHR) {
        int d0 = c << 2, d1 = d0 + (NTHR << 2);
        float4 a0 = ldw(ur + d0), b0 = ldw(uz + d0), e0 = ldw(un + d0);
        float4 a1 = ldw(ur + d1), b1 = ldw(uz + d1), e1 = ldw(un + d1);
        float4 h0 = ldx(hprev + d0), h1v = ldx(hprev + d1);
        acc[3] += dot4(a0, h0); acc[4] += dot4(b0, h0); acc[5] += dot4(e0, h0);
        acc[3] += dot4(a1, h1v); acc[4] += dot4(b1, h1v); acc[5] += dot4(e1, h1v);
    }
    if (c < nvh) {
        int d0 = c << 2;
        float4 a0 = ldw(ur + d0), b0 = ldw(uz + d0), e0 = ldw(un + d0);
        float4 h0 = ldx(hprev + d0);
        acc[3] += dot4(a0, h0); acc[4] += dot4(b0, h0); acc[5] += dot4(e0, h0);
    }

    float s[6];
    blockReduce<6>(acc, s);
    if (threadIdx.x == 0) {
        float r = sigm(s[0] + bih[j] + s[3] + bhh[j]);
        float z = sigm(s[1] + bih[H + j] + s[4] + bhh[H + j]);
        float n = tanhf(s[2] + bih[2 * H + j] + r * (s[5] + bhh[2 * H + j]));
        newout[j] = (1.0f - z) * n + z * hprev[j];
    }
}

// -------- dual-stream GRU unit (k/f cells) --------
__device__ __forceinline__ void gru_unit_dual(
    const float* __restrict__ wih, const float* __restrict__ whh,
    const float* __restrict__ bih, const float* __restrict__ bhh,
    const float* __restrict__ x1bufs, const float* __restrict__ x2bufs, int pad, int D,
    const float* __restrict__ h1, const float* __restrict__ h2, int H, int j,
    float* __restrict__ out1, float* __restrict__ out2)
{
    float acc[12] = {0, 0, 0, 0, 0, 0, 0, 0, 0, 0, 0, 0};
    const int head = (4 - (j & 3)) & 3;
    const int off  = head * pad + cls_off(head);
    const float* x1c = x1bufs + off;
    const float* x2c = x2bufs + off;
    const float* wr = wih + (size_t)j * D;
    const float* wz = wih + (size_t)(H + j) * D;
    const float* wn = wih + (size_t)(2 * H + j) * D;
    const int nvec = (D - head) >> 2;
    const int tail = D - head - (nvec << 2);

    if (threadIdx.x < (unsigned)head) {
        int d = threadIdx.x;
        float a = x1c[d], b = x2c[d];
        float w0 = wr[d], w1 = wz[d], w2 = wn[d];
        acc[0] += w0 * a; acc[1] += w1 * a; acc[2] += w2 * a;
        acc[3] += w0 * b; acc[4] += w1 * b; acc[5] += w2 * b;
    }
    int c = threadIdx.x;
    for (; c + NTHR < nvec; c += 2 * NTHR) {
        int d0 = head + (c << 2), d1 = d0 + (NTHR << 2);
        float4 a0 = ldw(wr + d0), b0 = ldw(wz + d0), e0 = ldw(wn + d0);
        float4 a1 = ldw(wr + d1), b1 = ldw(wz + d1), e1 = ldw(wn + d1);
        float4 p0 = ldx(x1c + d0), q0 = ldx(x2c + d0);
        float4 p1 = ldx(x1c + d1), q1 = ldx(x2c + d1);
        acc[0] += dot4(a0, p0); acc[1] += dot4(b0, p0); acc[2] += dot4(e0, p0);
        acc[3] += dot4(a0, q0); acc[4] += dot4(b0, q0); acc[5] += dot4(e0, q0);
        acc[0] += dot4(a1, p1); acc[1] += dot4(b1, p1); acc[2] += dot4(e1, p1);
        acc[3] += dot4(a1, q1); acc[4] += dot4(b1, q1); acc[5] += dot4(e1, q1);
    }
    if (c < nvec) {
        int d0 = head + (c << 2);
        float4 a0 = ldw(wr + d0), b0 = ldw(wz + d0), e0 = ldw(wn + d0);
        float4 p0 = ldx(x1c + d0), q0 = ldx(x2c + d0);
        acc[0] += dot4(a0, p0); acc[1] += dot4(b0, p0); acc[2] += dot4(e0, p0);
        acc[3] += dot4(a0, q0); acc[4] += dot4(b0, q0); acc[5] += dot4(e0, q0);
    }
    if (threadIdx.x < (unsigned)tail) {
        int d = head + (nvec << 2) + threadIdx.x;
        float a = x1c[d], b = x2c[d];
        float w0 = wr[d], w1 = wz[d], w2 = wn[d];
        acc[0] += w0 * a; acc[1] += w1 * a; acc[2] += w2 * a;
        acc[3] += w0 * b; acc[4] += w1 * b; acc[5] += w2 * b;
    }

    const float* ur = whh + (size_t)j * H;
    const float* uz = whh + (size_t)(H + j) * H;
    const float* un = whh + (size_t)(2 * H + j) * H;
    const int nvh = H >> 2;
    c = threadIdx.x;
    for (; c + NTHR < nvh; c += 2 * NTHR) {
        int d0 = c << 2, d1 = d0 + (NTHR << 2);
        float4 a0 = ldw(ur + d0), b0 = ldw(uz + d0), e0 = ldw(un + d0);
        float4 a1 = ldw(ur + d1), b1 = ldw(uz + d1), e1 = ldw(un + d1);
        float4 p0 = ldx(h1 + d0), q0 = ldx(h2 + d0);
        float4 p1 = ldx(h1 + d1), q1 = ldx(h2 + d1);
        acc[6] += dot4(a0, p0); acc[7]  += dot4(b0, p0); acc[8]  += dot4(e0, p0);
        acc[9] += dot4(a0, q0); acc[10] += dot4(b0, q0); acc[11] += dot4(e0, q0);
        acc[6] += dot4(a1, p1); acc[7]  += dot4(b1, p1); acc[8]  += dot4(e1, p1);
        acc[9] += dot4(a1, q1); acc[10] += dot4(b1, q1); acc[11] += dot4(e1, q1);
    }
    if (c < nvh) {
        int d0 = c << 2;
        float4 a0 = ldw(ur + d0), b0 = ldw(uz + d0), e0 = ldw(un + d0);
        float4 p0 = ldx(h1 + d0), q0 = ldx(h2 + d0);
        acc[6] += dot4(a0, p0); acc[7]  += dot4(b0, p0); acc[8]  += dot4(e0, p0);
        acc[9] += dot4(a0, q0); acc[10] += dot4(b0, q0); acc[11] += dot4(e0, q0);
    }

    float s[12];
    blockReduce<12>(acc, s);
    if (threadIdx.x == 0) {
        float br = bih[j], bz = bih[H + j], bn = bih[2 * H + j];
        float cr = bhh[j], cz = bhh[H + j], cn = bhh[2 * H + j];
        {
            float r = sigm(s[0] + br + s[6] + cr);
            float z = sigm(s[1] + bz + s[7] + cz);
            float n = tanhf(s[2] + bn + r * (s[8] + cn));
            out1[j] = (1.0f - z) * n + z * h1[j];
        }
        {
            float r = sigm(s[3] + br + s[9] + cr);
            float z = sigm(s[4] + bz + s[10] + cz);
            float n = tanhf(s[5] + bn + r * (s[11] + cn));
            out2[j] = (1.0f - z) * n + z * h2[j];
        }
    }
}

// ---------------- K0: prep ----------------
__global__ __launch_bounds__(NTHR) void k_prep(
    const float* __restrict__ x,
    const float* __restrict__ h1s, const float* __restrict__ h2s,
    const float* __restrict__ k1s, const float* __restrict__ k2s,
    const float* __restrict__ f1s, const float* __restrict__ f2s)
{
    int idx = blockIdx.x * blockDim.x + threadIdx.x;   // [0, 4*OSC)
    int h = idx >> 11;
    int i = idx & (OSC - 1);
    if (blockIdx.x == 0 && threadIdx.x < 4) {
        int c = threadIdx.x;
        int o = cls_off(c);
        g_xm [c * XM_P + o + 0] = x[0];
        g_xm [c * XM_P + o + 1] = x[1];
        g_xm [c * XM_P + o + 2] = x[8];
        g_xm [c * XM_P + o + 3] = x[9];
        g_xm [c * XM_P + o + 4] = x[10];
        g_xk1[c * XK_P + o] = x[3]; g_xk2[c * XK_P + o] = x[6];
        g_xf1[c * XF_P + o] = x[4]; g_xf2[c * XF_P + o] = x[7];
        if (c == 0) { g_hx[0] = x[2]; g_hx[1] = x[5]; }
    }
    {
        float h1v = h1s[i], h2v = h2s[i], f1v = f1s[i], f2v = f2s[i];
        float k1v = k1s[i], k2v = k2s[i];
        int o = cls_off(h);
        g_xm [h * XM_P + o + 5 + i]        = h1v;
        g_xm [h * XM_P + o + 5 + OSC + i]  = h2v;
        g_xk1[h * XK_P + o + 1 + i]        = h1v;
        g_xk1[h * XK_P + o + 1 + OSC + i]  = f1v;
        g_xk2[h * XK_P + o + 1 + i]        = h2v;
        g_xk2[h * XK_P + o + 1 + OSC + i]  = f2v;
        g_xf1[h * XF_P + o + 1 + i]        = f1v;
        g_xf2[h * XF_P + o + 1 + i]        = f2v;
        g_sk1[h * SH_P + h + i] = k1v;
        g_sk2[h * SH_P + h + i] = k2v;
    }
}

// ---------------- K1: m + k + f + h_ind (all input-only; no sync) ----------------
__global__ __launch_bounds__(NTHR) void k_main(
    const float* __restrict__ m_s,
    const float* __restrict__ h1s, const float* __restrict__ h2s,
    const float* __restrict__ k1s, const float* __restrict__ k2s,
    const float* __restrict__ f1s, const float* __restrict__ f2s,
    const float* __restrict__ m_wih, const float* __restrict__ m_whh,
    const float* __restrict__ m_bih, const float* __restrict__ m_bhh,
    const float* __restrict__ h_wih, const float* __restrict__ h_whh,
    const float* __restrict__ k_wih, const float* __restrict__ k_whh,
    const float* __restrict__ k_bih, const float* __restrict__ k_bhh,
    const float* __restrict__ f_wih, const float* __restrict__ f_whh,
    const float* __restrict__ f_bih, const float* __restrict__ f_bhh)
{
    const int b = blockIdx.x;
    const int tid = threadIdx.x;

    if (b < 4096) {
        gru_unit_single(m_wih, m_whh, m_bih, m_bhh, g_xm, XM_P, 5 + 2 * OSC,
                        m_s, MH, b, g_mnew);
    } else if (b < 6144) {
        gru_unit_dual(k_wih, k_whh, k_bih, k_bhh, g_xk1, g_xk2, XK_P, 1 + 2 * OSC,
                      k1s, k2s, OSC, b - 4096, g_k1new, g_k2new);
    } else if (b < 8192) {
        gru_unit_dual(f_wih, f_whh, f_bih, f_bhh, g_xf1, g_xf2, XF_P, 1 + OSC,
                      f1s, f2s, OSC, b - 6144, g_f1new, g_f2new);
    } else {
        // ---- h_ind: whh + wih col0 + wih cols [2049,4097) -> partials ----
        const int j = b - 8192;
        const int a = (j + 1) & 3;
        const int head = (4 - a) & 3;
        float acc[12] = {0,0,0,0,0,0,0,0,0,0,0,0};

        {
            const float* ur = h_whh + (size_t)j * OSC;
            const float* uz = ur + (size_t)OSC * OSC;
            const float* un = uz + (size_t)OSC * OSC;
            int d0 = tid << 2, d1 = d0 + 1024;
            float4 u0 = ldw(ur + d0), u1 = ldw(uz + d0), u2 = ldw(un + d0);
            float4 u3 = ldw(ur + d1), u4 = ldw(uz + d1), u5 = ldw(un + d1);
            float4 p0 = ldx(h1s + d0), p1 = ldx(h1s + d1);
            float4 q0 = ldx(h2s + d0), q1 = ldx(h2s + d1);
            acc[6] = dot4(u0, p0) + dot4(u3, p1);
            acc[7] = dot4(u1, p0) + dot4(u4, p1);
            acc[8] = dot4(u2, p0) + dot4(u5, p1);
            acc[9]  = dot4(u0, q0) + dot4(u3, q1);
            acc[10] = dot4(u1, q0) + dot4(u4, q1);
            acc[11] = dot4(u2, q0) + dot4(u5, q1);
        }
        {
            const float* wr = h_wih + (size_t)j * 4097 + 2049;
            const float* wz = wr + (size_t)OSC * 4097;
            const float* wn = wz + (size_t)OSC * 4097;
            const float* xk1 = g_sk1 + a * SH_P + a;
            const float* xk2 = g_sk2 + a * SH_P + a;
            const int nv = (2048 - head) >> 2;
            int e0 = head + (tid << 2);
            float4 w0 = ldw(wr + e0), w1 = ldw(wz + e0), w2 = ldw(wn + e0);
            float4 xp = ldx(xk1 + e0), xq = ldx(xk2 + e0);
            acc[0] += dot4(w0, xp); acc[1] += dot4(w1, xp); acc[2] += dot4(w2, xp);
            acc[3] += dot4(w0, xq); acc[4] += dot4(w1, xq); acc[5] += dot4(w2, xq);
            if (tid + NTHR < nv) {
                int e1 = head + ((tid + NTHR) << 2);
                float4 w3 = ldw(wr + e1), w4 = ldw(wz + e1), w5 = ldw(wn + e1);
                float4 xp1 = ldx(xk1 + e1), xq1 = ldx(xk2 + e1);
                acc[0] += dot4(w3, xp1); acc[1] += dot4(w4, xp1); acc[2] += dot4(w5, xp1);
                acc[3] += dot4(w3, xq1); acc[4] += dot4(w4, xq1); acc[5] += dot4(w5, xq1);
            }
            if (tid < head) {
                float xa = xk1[tid], xb = xk2[tid];
                float s0 = wr[tid], s1 = wz[tid], s2 = wn[tid];
                acc[0] += s0 * xa; acc[1] += s1 * xa; acc[2] += s2 * xa;
                acc[3] += s0 * xb; acc[4] += s1 * xb; acc[5] += s2 * xb;
            }
            const int tstart = head + (nv << 2);
            const int tcount = 2048 - tstart;
            if (tid >= 32 && tid - 32 < tcount) {
                int t = tstart + (tid - 32);
                float xa = xk1[t], xb = xk2[t];
                float s0 = wr[t], s1 = wz[t], s2 = wn[t];
                acc[0] += s0 * xa; acc[1] += s1 * xa; acc[2] += s2 * xa;
                acc[3] += s0 * xb; acc[4] += s1 * xb; acc[5] += s2 * xb;
            }
            if (tid == 64) {
                const float* w0p = h_wih + (size_t)j * 4097;
                float w0 = w0p[0];
                float w1 = w0p[(size_t)OSC * 4097];
                float w2 = w0p[(size_t)2 * OSC * 4097];
                float hx1 = g_hx[0], hx2 = g_hx[1];
                acc[0] += w0 * hx1; acc[1] += w1 * hx1; acc[2] += w2 * hx1;
                acc[3] += w0 * hx2; acc[4] += w1 * hx2; acc[5] += w2 * hx2;
            }
        }
        float s[12];
        blockReduce<12>(acc, s);
        if (tid == 0) {
#pragma unroll
            for (int i = 0; i < 12; i++) g_hp[j][i] = s[i];
        }
    }
}

// ---------------- K2: mout rows + k/f heads (no internal deps) ----------------
__global__ __launch_bounds__(NTHR) void k_mout(
    const float* __restrict__ w, const float* __restrict__ bias,
    const float* __restrict__ k_ow, const float* __restrict__ k_ob,
    const float* __restrict__ f_ow, const float* __restrict__ f_ob,
    float* __restrict__ out)
{
    const int b = blockIdx.x;
    const int tid = threadIdx.x;
    if (b < 4096) {
        const int r = b;
        const float* wr = w + (size_t)r * MH;
        int d0 = tid << 2;
        float4 a0 = ldw(wr + d0),        a1 = ldw(wr + d0 + 1024);
        float4 a2 = ldw(wr + d0 + 2048), a3 = ldw(wr + d0 + 3072);
        float4 m0 = ldx(g_mnew + d0),        m1 = ldx(g_mnew + d0 + 1024);
        float4 m2 = ldx(g_mnew + d0 + 2048), m3 = ldx(g_mnew + d0 + 3072);
        float acc[1];
        acc[0] = dot4(a0, m0) + dot4(a1, m1) + dot4(a2, m2) + dot4(a3, m3);
        float s[1];
        blockReduce<1>(acc, s);
        if (tid == 0) {
            float v = s[0] + bias[r];
            if (r < OSC) {
#pragma unroll
                for (int o = 0; o < 4; o++) g_so1[o * SH_P + o + r] = v;
            } else {
                int rr = r - OSC;
#pragma unroll
                for (int o = 0; o < 4; o++) g_so2[o * SH_P + o + rr] = v;
            }
        }
    } else {
        const int hb = b - 4096;
        const float* vec;
        const float* hw;
        const float* bp;
        int oidx;
        switch (hb) {
            case 0:  vec = g_k1new; hw = k_ow; bp = k_ob; oidx = 1; break;
            case 1:  vec = g_f1new; hw = f_ow; bp = f_ob; oidx = 2; break;
            case 2:  vec = g_k2new; hw = k_ow; bp = k_ob; oidx = 4; break;
            default: vec = g_f2new; hw = f_ow; bp = f_ob; oidx = 5; break;
        }
        int d0 = tid << 2;
        float4 a0 = ldx(hw + d0), a1 = ldx(hw + d0 + 1024);
        float4 v0 = ldx(vec + d0), v1 = ldx(vec + d0 + 1024);
        float acc[1];
        acc[0] = dot4(a0, v0) + dot4(a1, v1);
        float s[1];
        blockReduce<1>(acc, s);
        if (tid == 0) out[oidx] = s[0] + bp[0];
    }
}

// ---------------- K3: h_dep — TWO rows per block sharing x (1:1 w:x ratio) ----------------
// block b: gate g = b >> 10, j = b & 1023. Rows g*2048+j and g*2048+j+1024 (same class).
__global__ __launch_bounds__(NTHR) void k_hdepG2(
    const float* __restrict__ h_wih)
{
    const int b = blockIdx.x;
    const int g = b >> 10;
    const int j = b & 1023;
    const int j2 = j + 1024;
    const int tid = threadIdx.x;
    const int a = (j + 1) & 3;           // same class for j and j2
    const int head = (4 - a) & 3;
    const float* w1row = h_wih + (size_t)(g * OSC + j) * 4097 + 1;
    const float* w2row = h_wih + (size_t)(g * OSC + j2) * 4097 + 1;
    const float* xo1 = g_so1 + a * SH_P + a;
    const float* xo2 = g_so2 + a * SH_P + a;
    const int nv = (2048 - head) >> 2;   // 511 or 512

    // acc: {w1.xo1, w1.xo2, w2.xo1, w2.xo2}
    float acc[4] = {0, 0, 0, 0};
    int e0 = head + (tid << 2);
    float4 wa0 = ldw(w1row + e0);
    float4 wb0 = ldw(w2row + e0);
    float4 p0 = ldx(xo1 + e0), q0 = ldx(xo2 + e0);
    bool ok1 = (tid + NTHR < nv);
    int e1 = e0 + (NTHR << 2);
    if (ok1) {
        float4 wa1 = ldw(w1row + e1);
        float4 wb1 = ldw(w2row + e1);
        float4 p1 = ldx(xo1 + e1), q1 = ldx(xo2 + e1);
        acc[0] += dot4(wa1, p1); acc[1] += dot4(wa1, q1);
        acc[2] += dot4(wb1, p1); acc[3] += dot4(wb1, q1);
    }
    acc[0] += dot4(wa0, p0); acc[1] += dot4(wa0, q0);
    acc[2] += dot4(wb0, p0); acc[3] += dot4(wb0, q0);
    // head scalars
    if (tid < head) {
        float xa = xo1[tid], xb = xo2[tid];
        float v1 = w1row[tid], v2 = w2row[tid];
        acc[0] += v1 * xa; acc[1] += v1 * xb;
        acc[2] += v2 * xa; acc[3] += v2 * xb;
    }
    // tail scalars
    {
        const int tstart = head + (nv << 2);
        const int tcount = 2048 - tstart;    // 0..3
        if (tid >= 32 && tid - 32 < tcount) {
            int t = tstart + (tid - 32);
            float xa = xo1[t], xb = xo2[t];
            float v1 = w1row[t], v2 = w2row[t];
            acc[0] += v1 * xa; acc[1] += v1 * xb;
            acc[2] += v2 * xa; acc[3] += v2 * xb;
        }
    }

    float s[4];
    blockReduce<4>(acc, s);
    if (tid == 0) {
        g_hq[j][2 * g]      = s[0];
        g_hq[j][2 * g + 1]  = s[1];
        g_hq[j2][2 * g]     = s[2];
        g_hq[j2][2 * g + 1] = s[3];
    }
}

// ---------------- K4: gate epilogue, one thread per h-unit ----------------
__global__ __launch_bounds__(NTHR) void k_gates(
    const float* __restrict__ h_bih, const float* __restrict__ h_bhh,
    const float* __restrict__ h1s, const float* __restrict__ h2s)
{
    const int j = blockIdx.x * NTHR + threadIdx.x;   // 8 blocks -> 2048
    const float4* hp4 = reinterpret_cast<const float4*>(g_hp[j]);
    const float4* hq4 = reinterpret_cast<const float4*>(g_hq[j]);
    float4 pa = hp4[0], pb = hp4[1], pc = hp4[2];
    float4 qa = hq4[0], qb = hq4[1];
    // hp: [gi1 r z n | gi2 r z n | gh1 r z n | gh2 r z n]
    // hq: [r_s1 r_s2 z_s1 z_s2 n_s1 n_s2 _ _]  (index 2g+s)
    float gi1r = pa.x + qa.x;
    float gi1z = pa.y + qa.z;
    float gi1n = pa.z + qb.x;
    float gi2r = pa.w + qa.y;
    float gi2z = pb.x + qa.w;
    float gi2n = pb.y + qb.y;
    float gh1r = pb.z, gh1z = pb.w, gh1n = pc.x;
    float gh2r = pc.y, gh2z = pc.z, gh2n = pc.w;
    float br = h_bih[j], bz = h_bih[OSC + j], bn = h_bih[2 * OSC + j];
    float cr = h_bhh[j], cz = h_bhh[OSC + j], cn = h_bhh[2 * OSC + j];
    {
        float r = sigm(gi1r + br + gh1r + cr);
        float z = sigm(gi1z + bz + gh1z + cz);
        float n = tanhf(gi1n + bn + r * (gh1n + cn));
        g_h1new[j] = (1.0f - z) * n + z * h1s[j];
    }
    {
        float r = sigm(gi2r + br + gh2r + cr);
        float z = sigm(gi2z + bz + gh2z + cz);
        float n = tanhf(gi2n + bn + r * (gh2n + cn));
        g_h2new[j] = (1.0f - z) * n + z * h2s[j];
    }
}

// ---------------- K5: two h output dot products ----------------
__global__ __launch_bounds__(NTHR) void k_heads_h(
    const float* __restrict__ h_ow, const float* __restrict__ h_ob,
    float* __restrict__ out)
{
    const int b = blockIdx.x;   // 0 -> h1 (out[0]), 1 -> h2 (out[3])
    const float* vec = (b == 0) ? g_h1new : g_h2new;
    int d0 = threadIdx.x << 2;
    float4 a0 = ldx(h_ow + d0), a1 = ldx(h_ow + d0 + 1024);
    float4 v0 = ldx(vec + d0), v1 = ldx(vec + d0 + 1024);
    float acc[1];
    acc[0] = dot4(a0, v0) + dot4(a1, v1);
    float s[1];
    blockReduce<1>(acc, s);
    if (threadIdx.x == 0) out[(b == 0) ? 0 : 3] = s[0] + h_ob[0];
}

// ---------------- launch ----------------
extern "C" void kernel_launch(void* const* d_in, const int* in_sizes, int n_in,
                              void* d_out, int out_size)
{
    const float* x      = (const float*)d_in[0];
    const float* m_s    = (const float*)d_in[1];
    const float* h1_s   = (const float*)d_in[2];
    const float* h2_s   = (const float*)d_in[3];
    const float* k1_s   = (const float*)d_in[4];
    const float* k2_s   = (const float*)d_in[5];
    const float* f1_s   = (const float*)d_in[6];
    const float* f2_s   = (const float*)d_in[7];
    const float* m_wih  = (const float*)d_in[8];
    const float* m_whh  = (const float*)d_in[9];
    const float* m_bih  = (const float*)d_in[10];
    const float* m_bhh  = (const float*)d_in[11];
    const float* m_ow   = (const float*)d_in[12];
    const float* m_ob   = (const float*)d_in[13];
    const float* h_wih  = (const float*)d_in[14];
    const float* h_whh  = (const float*)d_in[15];
    const float* h_bih  = (const float*)d_in[16];
    const float* h_bhh  = (const float*)d_in[17];
    const float* h_ow   = (const float*)d_in[18];
    const float* h_ob   = (const float*)d_in[19];
    const float* k_wih  = (const float*)d_in[20];
    const float* k_whh  = (const float*)d_in[21];
    const float* k_bih  = (const float*)d_in[22];
    const float* k_bhh  = (const float*)d_in[23];
    const float* k_ow   = (const float*)d_in[24];
    const float* k_ob   = (const float*)d_in[25];
    const float* f_wih  = (const float*)d_in[26];
    const float* f_whh  = (const float*)d_in[27];
    const float* f_bih  = (const float*)d_in[28];
    const float* f_bhh  = (const float*)d_in[29];
    const float* f_ow   = (const float*)d_in[30];
    const float* f_ob   = (const float*)d_in[31];
    float* out = (float*)d_out;

    k_prep<<<(4 * OSC) / NTHR, NTHR>>>(x, h1_s, h2_s, k1_s, k2_s, f1_s, f2_s);
    k_main<<<10240, NTHR>>>(m_s, h1_s, h2_s, k1_s, k2_s, f1_s, f2_s,
                            m_wih, m_whh, m_bih, m_bhh,
                            h_wih, h_whh,
                            k_wih, k_whh, k_bih, k_bhh,
                            f_wih, f_whh, f_bih, f_bhh);
    k_mout<<<4100, NTHR>>>(m_ow, m_ob, k_ow, k_ob, f_ow, f_ob, out);
    k_hdepG2<<<3 * 1024, NTHR>>>(h_wih);
    k_gates<<<OSC / NTHR, NTHR>>>(h_bih, h_bhh, h1_s, h2_s);
    k_heads_h<<<2, NTHR>>>(h_ow, h_ob, out);
}

// round 14
// speedup vs baseline: 1.0691x; 1.0002x over previous
#include <cuda_runtime.h>

#define OSC 2048
#define MH  4096
#define NTHR 256

#define XM_P  4104
#define XK_P  4100
#define XF_P  2052
#define SH_P  2052   // shifted 2048-vectors (k-state, out_m halves)

// ---------------- scratch (no allocs allowed) ----------------
__device__ __align__(16) float g_xm [4 * XM_P];
__device__ __align__(16) float g_xk1[4 * XK_P], g_xk2[4 * XK_P];
__device__ __align__(16) float g_xf1[4 * XF_P], g_xf2[4 * XF_P];
__device__ __align__(16) float g_sk1[4 * SH_P], g_sk2[4 * SH_P];  // k1_s/k2_s shifted
__device__ __align__(16) float g_so1[4 * SH_P], g_so2[4 * SH_P];  // out_m halves shifted
__device__ __align__(16) float g_mnew[MH];
__device__ __align__(16) float g_k1new[OSC], g_k2new[OSC];
__device__ __align__(16) float g_f1new[OSC], g_f2new[OSC];
__device__ __align__(16) float g_hp[OSC][12];  // h_ind partials: [gi1(3), gi2(3), gh1(3), gh2(3)]
__device__ __align__(32) float g_hq[OSC][8];   // h_dep partials: [gate g, stream s] at 2g+s
__device__ float g_hx[2];                       // x[2], x[5]
__device__ __align__(8) float g_ghp[8][2];      // per-block h-head partials
__device__ unsigned g_ghc;                      // ticket for k_gh finisher

__device__ __forceinline__ float sigm(float v) { return 1.0f / (1.0f + __expf(-v)); }
__device__ __forceinline__ int cls_off(int h) { return (4 - h) & 3; }

__device__ __forceinline__ float4 ldw(const float* p) {
    return __ldcs(reinterpret_cast<const float4*>(p));
}
__device__ __forceinline__ float4 ldx(const float* p) {
    return *reinterpret_cast<const float4*>(p);
}
__device__ __forceinline__ float dot4(float4 a, float4 b) {
    return a.x * b.x + a.y * b.y + a.z * b.z + a.w * b.w;
}

template <int NS>
__device__ __forceinline__ void blockReduce(float (&acc)[NS], float (&out)[NS]) {
    __shared__ float sm[NS][NTHR / 32];
    const int lane = threadIdx.x & 31;
    const int wid  = threadIdx.x >> 5;
#pragma unroll
    for (int s = 0; s < NS; s++) {
        float v = acc[s];
        v += __shfl_down_sync(0xffffffffu, v, 16);
        v += __shfl_down_sync(0xffffffffu, v, 8);
        v += __shfl_down_sync(0xffffffffu, v, 4);
        v += __shfl_down_sync(0xffffffffu, v, 2);
        v += __shfl_down_sync(0xffffffffu, v, 1);
        if (lane == 0) sm[s][wid] = v;
    }
    __syncthreads();
    if (threadIdx.x == 0) {
#pragma unroll
        for (int s = 0; s < NS; s++) {
            float v = 0.0f;
#pragma unroll
            for (int w = 0; w < NTHR / 32; w++) v += sm[s][w];
            out[s] = v;
        }
    }
}

// -------- single-stream GRU unit (m cell) --------
__device__ __forceinline__ void gru_unit_single(
    const float* __restrict__ wih, const float* __restrict__ whh,
    const float* __restrict__ bih, const float* __restrict__ bhh,
    const float* __restrict__ xbufs, int pad, int D,
    const float* __restrict__ hprev, int H, int j,
    float* __restrict__ newout)
{
    float acc[6] = {0, 0, 0, 0, 0, 0};
    const int head = (4 - (j & 3)) & 3;
    const float* xc = xbufs + head * pad + cls_off(head);
    const float* wr = wih + (size_t)j * D;
    const float* wz = wih + (size_t)(H + j) * D;
    const float* wn = wih + (size_t)(2 * H + j) * D;
    const int nvec = (D - head) >> 2;
    const int tail = D - head - (nvec << 2);

    if (threadIdx.x < (unsigned)head) {
        int d = threadIdx.x;
        float xv = xc[d];
        acc[0] += wr[d] * xv; acc[1] += wz[d] * xv; acc[2] += wn[d] * xv;
    }
    int c = threadIdx.x;
    for (; c + NTHR < nvec; c += 2 * NTHR) {
        int d0 = head + (c << 2);
        int d1 = d0 + (NTHR << 2);
        float4 a0 = ldw(wr + d0), b0 = ldw(wz + d0), e0 = ldw(wn + d0);
        float4 a1 = ldw(wr + d1), b1 = ldw(wz + d1), e1 = ldw(wn + d1);
        float4 x0 = ldx(xc + d0), x1 = ldx(xc + d1);
        acc[0] += dot4(a0, x0); acc[1] += dot4(b0, x0); acc[2] += dot4(e0, x0);
        acc[0] += dot4(a1, x1); acc[1] += dot4(b1, x1); acc[2] += dot4(e1, x1);
    }
    if (c < nvec) {
        int d0 = head + (c << 2);
        float4 a0 = ldw(wr + d0), b0 = ldw(wz + d0), e0 = ldw(wn + d0);
        float4 x0 = ldx(xc + d0);
        acc[0] += dot4(a0, x0); acc[1] += dot4(b0, x0); acc[2] += dot4(e0, x0);
    }
    if (threadIdx.x < (unsigned)tail) {
        int d = head + (nvec << 2) + threadIdx.x;
        float xv = xc[d];
        acc[0] += wr[d] * xv; acc[1] += wz[d] * xv; acc[2] += wn[d] * xv;
    }

    const float* ur = whh + (size_t)j * H;
    const float* uz = whh + (size_t)(H + j) * H;
    const float* un = whh + (size_t)(2 * H + j) * H;
    const int nvh = H >> 2;
    c = threadIdx.x;
    for (; c + NTHR < nvh; c += 2 * NTHR) {
        int d0 = c << 2, d1 = d0 + (NTHR << 2);
        float4 a0 = ldw(ur + d0), b0 = ldw(uz + d0), e0 = ldw(un + d0);
        float4 a1 = ldw(ur + d1), b1 = ldw(uz + d1), e1 = ldw(un + d1);
        float4 h0 = ldx(hprev + d0), h1v = ldx(hprev + d1);
        acc[3] += dot4(a0, h0); acc[4] += dot4(b0, h0); acc[5] += dot4(e0, h0);
        acc[3] += dot4(a1, h1v); acc[4] += dot4(b1, h1v); acc[5] += dot4(e1, h1v);
    }
    if (c < nvh) {
        int d0 = c << 2;
        float4 a0 = ldw(ur + d0), b0 = ldw(uz + d0), e0 = ldw(un + d0);
        float4 h0 = ldx(hprev + d0);
        acc[3] += dot4(a0, h0); acc[4] += dot4(b0, h0); acc[5] += dot4(e0, h0);
    }

    float s[6];
    blockReduce<6>(acc, s);
    if (threadIdx.x == 0) {
        float r = sigm(s[0] + bih[j] + s[3] + bhh[j]);
        float z = sigm(s[1] + bih[H + j] + s[4] + bhh[H + j]);
        float n = tanhf(s[2] + bih[2 * H + j] + r * (s[5] + bhh[2 * H + j]));
        newout[j] = (1.0f - z) * n + z * hprev[j];
    }
}

// -------- dual-stream GRU unit (k/f cells) --------
__device__ __forceinline__ void gru_unit_dual(
    const float* __restrict__ wih, const float* __restrict__ whh,
    const float* __restrict__ bih, const float* __restrict__ bhh,
    const float* __restrict__ x1bufs, const float* __restrict__ x2bufs, int pad, int D,
    const float* __restrict__ h1, const float* __restrict__ h2, int H, int j,
    float* __restrict__ out1, float* __restrict__ out2)
{
    float acc[12] = {0, 0, 0, 0, 0, 0, 0, 0, 0, 0, 0, 0};
    const int head = (4 - (j & 3)) & 3;
    const int off  = head * pad + cls_off(head);
    const float* x1c = x1bufs + off;
    const float* x2c = x2bufs + off;
    const float* wr = wih + (size_t)j * D;
    const float* wz = wih + (size_t)(H + j) * D;
    const float* wn = wih + (size_t)(2 * H + j) * D;
    const int nvec = (D - head) >> 2;
    const int tail = D - head - (nvec << 2);

    if (threadIdx.x < (unsigned)head) {
        int d = threadIdx.x;
        float a = x1c[d], b = x2c[d];
        float w0 = wr[d], w1 = wz[d], w2 = wn[d];
        acc[0] += w0 * a; acc[1] += w1 * a; acc[2] += w2 * a;
        acc[3] += w0 * b; acc[4] += w1 * b; acc[5] += w2 * b;
    }
    int c = threadIdx.x;
    for (; c + NTHR < nvec; c += 2 * NTHR) {
        int d0 = head + (c << 2), d1 = d0 + (NTHR << 2);
        float4 a0 = ldw(wr + d0), b0 = ldw(wz + d0), e0 = ldw(wn + d0);
        float4 a1 = ldw(wr + d1), b1 = ldw(wz + d1), e1 = ldw(wn + d1);
        float4 p0 = ldx(x1c + d0), q0 = ldx(x2c + d0);
        float4 p1 = ldx(x1c + d1), q1 = ldx(x2c + d1);
        acc[0] += dot4(a0, p0); acc[1] += dot4(b0, p0); acc[2] += dot4(e0, p0);
        acc[3] += dot4(a0, q0); acc[4] += dot4(b0, q0); acc[5] += dot4(e0, q0);
        acc[0] += dot4(a1, p1); acc[1] += dot4(b1, p1); acc[2] += dot4(e1, p1);
        acc[3] += dot4(a1, q1); acc[4] += dot4(b1, q1); acc[5] += dot4(e1, q1);
    }
    if (c < nvec) {
        int d0 = head + (c << 2);
        float4 a0 = ldw(wr + d0), b0 = ldw(wz + d0), e0 = ldw(wn + d0);
        float4 p0 = ldx(x1c + d0), q0 = ldx(x2c + d0);
        acc[0] += dot4(a0, p0); acc[1] += dot4(b0, p0); acc[2] += dot4(e0, p0);
        acc[3] += dot4(a0, q0); acc[4] += dot4(b0, q0); acc[5] += dot4(e0, q0);
    }
    if (threadIdx.x < (unsigned)tail) {
        int d = head + (nvec << 2) + threadIdx.x;
        float a = x1c[d], b = x2c[d];
        float w0 = wr[d], w1 = wz[d], w2 = wn[d];
        acc[0] += w0 * a; acc[1] += w1 * a; acc[2] += w2 * a;
        acc[3] += w0 * b; acc[4] += w1 * b; acc[5] += w2 * b;
    }

    const float* ur = whh + (size_t)j * H;
    const float* uz = whh + (size_t)(H + j) * H;
    const float* un = whh + (size_t)(2 * H + j) * H;
    const int nvh = H >> 2;
    c = threadIdx.x;
    for (; c + NTHR < nvh; c += 2 * NTHR) {
        int d0 = c << 2, d1 = d0 + (NTHR << 2);
        float4 a0 = ldw(ur + d0), b0 = ldw(uz + d0), e0 = ldw(un + d0);
        float4 a1 = ldw(ur + d1), b1 = ldw(uz + d1), e1 = ldw(un + d1);
        float4 p0 = ldx(h1 + d0), q0 = ldx(h2 + d0);
        float4 p1 = ldx(h1 + d1), q1 = ldx(h2 + d1);
        acc[6] += dot4(a0, p0); acc[7]  += dot4(b0, p0); acc[8]  += dot4(e0, p0);
        acc[9] += dot4(a0, q0); acc[10] += dot4(b0, q0); acc[11] += dot4(e0, q0);
        acc[6] += dot4(a1, p1); acc[7]  += dot4(b1, p1); acc[8]  += dot4(e1, p1);
        acc[9] += dot4(a1, q1); acc[10] += dot4(b1, q1); acc[11] += dot4(e1, q1);
    }
    if (c < nvh) {
        int d0 = c << 2;
        float4 a0 = ldw(ur + d0), b0 = ldw(uz + d0), e0 = ldw(un + d0);
        float4 p0 = ldx(h1 + d0), q0 = ldx(h2 + d0);
        acc[6] += dot4(a0, p0); acc[7]  += dot4(b0, p0); acc[8]  += dot4(e0, p0);
        acc[9] += dot4(a0, q0); acc[10] += dot4(b0, q0); acc[11] += dot4(e0, q0);
    }

    float s[12];
    blockReduce<12>(acc, s);
    if (threadIdx.x == 0) {
        float br = bih[j], bz = bih[H + j], bn = bih[2 * H + j];
        float cr = bhh[j], cz = bhh[H + j], cn = bhh[2 * H + j];
        {
            float r = sigm(s[0] + br + s[6] + cr);
            float z = sigm(s[1] + bz + s[7] + cz);
            float n = tanhf(s[2] + bn + r * (s[8] + cn));
            out1[j] = (1.0f - z) * n + z * h1[j];
        }
        {
            float r = sigm(s[3] + br + s[9] + cr);
            float z = sigm(s[4] + bz + s[10] + cz);
            float n = tanhf(s[5] + bn + r * (s[11] + cn));
            out2[j] = (1.0f - z) * n + z * h2[j];
        }
    }
}

// ---------------- K0: prep ----------------
__global__ __launch_bounds__(NTHR) void k_prep(
    const float* __restrict__ x,
    const float* __restrict__ h1s, const float* __restrict__ h2s,
    const float* __restrict__ k1s, const float* __restrict__ k2s,
    const float* __restrict__ f1s, const float* __restrict__ f2s)
{
    int idx = blockIdx.x * blockDim.x + threadIdx.x;   // [0, 4*OSC)
    int h = idx >> 11;
    int i = idx & (OSC - 1);
    if (blockIdx.x == 0 && threadIdx.x < 4) {
        int c = threadIdx.x;
        int o = cls_off(c);
        g_xm [c * XM_P + o + 0] = x[0];
        g_xm [c * XM_P + o + 1] = x[1];
        g_xm [c * XM_P + o + 2] = x[8];
        g_xm [c * XM_P + o + 3] = x[9];
        g_xm [c * XM_P + o + 4] = x[10];
        g_xk1[c * XK_P + o] = x[3]; g_xk2[c * XK_P + o] = x[6];
        g_xf1[c * XF_P + o] = x[4]; g_xf2[c * XF_P + o] = x[7];
        if (c == 0) { g_hx[0] = x[2]; g_hx[1] = x[5]; g_ghc = 0u; }
    }
    {
        float h1v = h1s[i], h2v = h2s[i], f1v = f1s[i], f2v = f2s[i];
        float k1v = k1s[i], k2v = k2s[i];
        int o = cls_off(h);
        g_xm [h * XM_P + o + 5 + i]        = h1v;
        g_xm [h * XM_P + o + 5 + OSC + i]  = h2v;
        g_xk1[h * XK_P + o + 1 + i]        = h1v;
        g_xk1[h * XK_P + o + 1 + OSC + i]  = f1v;
        g_xk2[h * XK_P + o + 1 + i]        = h2v;
        g_xk2[h * XK_P + o + 1 + OSC + i]  = f2v;
        g_xf1[h * XF_P + o + 1 + i]        = f1v;
        g_xf2[h * XF_P + o + 1 + i]        = f2v;
        g_sk1[h * SH_P + h + i] = k1v;
        g_sk2[h * SH_P + h + i] = k2v;
    }
}

// ---------------- K1: m + k + f + h_ind (all input-only; no sync) ----------------
__global__ __launch_bounds__(NTHR) void k_main(
    const float* __restrict__ m_s,
    const float* __restrict__ h1s, const float* __restrict__ h2s,
    const float* __restrict__ k1s, const float* __restrict__ k2s,
    const float* __restrict__ f1s, const float* __restrict__ f2s,
    const float* __restrict__ m_wih, const float* __restrict__ m_whh,
    const float* __restrict__ m_bih, const float* __restrict__ m_bhh,
    const float* __restrict__ h_wih, const float* __restrict__ h_whh,
    const float* __restrict__ k_wih, const float* __restrict__ k_whh,
    const float* __restrict__ k_bih, const float* __restrict__ k_bhh,
    const float* __restrict__ f_wih, const float* __restrict__ f_whh,
    const float* __restrict__ f_bih, const float* __restrict__ f_bhh)
{
    const int b = blockIdx.x;
    const int tid = threadIdx.x;

    if (b < 4096) {
        gru_unit_single(m_wih, m_whh, m_bih, m_bhh, g_xm, XM_P, 5 + 2 * OSC,
                        m_s, MH, b, g_mnew);
    } else if (b < 6144) {
        gru_unit_dual(k_wih, k_whh, k_bih, k_bhh, g_xk1, g_xk2, XK_P, 1 + 2 * OSC,
                      k1s, k2s, OSC, b - 4096, g_k1new, g_k2new);
    } else if (b < 8192) {
        gru_unit_dual(f_wih, f_whh, f_bih, f_bhh, g_xf1, g_xf2, XF_P, 1 + OSC,
                      f1s, f2s, OSC, b - 6144, g_f1new, g_f2new);
    } else {
        // ---- h_ind: whh + wih col0 + wih cols [2049,4097) -> partials ----
        const int j = b - 8192;
        const int a = (j + 1) & 3;
        const int head = (4 - a) & 3;
        float acc[12] = {0,0,0,0,0,0,0,0,0,0,0,0};

        {
            const float* ur = h_whh + (size_t)j * OSC;
            const float* uz = ur + (size_t)OSC * OSC;
            const float* un = uz + (size_t)OSC * OSC;
            int d0 = tid << 2, d1 = d0 + 1024;
            float4 u0 = ldw(ur + d0), u1 = ldw(uz + d0), u2 = ldw(un + d0);
            float4 u3 = ldw(ur + d1), u4 = ldw(uz + d1), u5 = ldw(un + d1);
            float4 p0 = ldx(h1s + d0), p1 = ldx(h1s + d1);
            float4 q0 = ldx(h2s + d0), q1 = ldx(h2s + d1);
            acc[6] = dot4(u0, p0) + dot4(u3, p1);
            acc[7] = dot4(u1, p0) + dot4(u4, p1);
            acc[8] = dot4(u2, p0) + dot4(u5, p1);
            acc[9]  = dot4(u0, q0) + dot4(u3, q1);
            acc[10] = dot4(u1, q0) + dot4(u4, q1);
            acc[11] = dot4(u2, q0) + dot4(u5, q1);
        }
        {
            const float* wr = h_wih + (size_t)j * 4097 + 2049;
            const float* wz = wr + (size_t)OSC * 4097;
            const float* wn = wz + (size_t)OSC * 4097;
            const float* xk1 = g_sk1 + a * SH_P + a;
            const float* xk2 = g_sk2 + a * SH_P + a;
            const int nv = (2048 - head) >> 2;
            int e0 = head + (tid << 2);
            float4 w0 = ldw(wr + e0), w1 = ldw(wz + e0), w2 = ldw(wn + e0);
            float4 xp = ldx(xk1 + e0), xq = ldx(xk2 + e0);
            acc[0] += dot4(w0, xp); acc[1] += dot4(w1, xp); acc[2] += dot4(w2, xp);
            acc[3] += dot4(w0, xq); acc[4] += dot4(w1, xq); acc[5] += dot4(w2, xq);
            if (tid + NTHR < nv) {
                int e1 = head + ((tid + NTHR) << 2);
                float4 w3 = ldw(wr + e1), w4 = ldw(wz + e1), w5 = ldw(wn + e1);
                float4 xp1 = ldx(xk1 + e1), xq1 = ldx(xk2 + e1);
                acc[0] += dot4(w3, xp1); acc[1] += dot4(w4, xp1); acc[2] += dot4(w5, xp1);
                acc[3] += dot4(w3, xq1); acc[4] += dot4(w4, xq1); acc[5] += dot4(w5, xq1);
            }
            if (tid < head) {
                float xa = xk1[tid], xb = xk2[tid];
                float s0 = wr[tid], s1 = wz[tid], s2 = wn[tid];
                acc[0] += s0 * xa; acc[1] += s1 * xa; acc[2] += s2 * xa;
                acc[3] += s0 * xb; acc[4] += s1 * xb; acc[5] += s2 * xb;
            }
            const int tstart = head + (nv << 2);
            const int tcount = 2048 - tstart;
            if (tid >= 32 && tid - 32 < tcount) {
                int t = tstart + (tid - 32);
                float xa = xk1[t], xb = xk2[t];
                float s0 = wr[t], s1 = wz[t], s2 = wn[t];
                acc[0] += s0 * xa; acc[1] += s1 * xa; acc[2] += s2 * xa;
                acc[3] += s0 * xb; acc[4] += s1 * xb; acc[5] += s2 * xb;
            }
            if (tid == 64) {
                const float* w0p = h_wih + (size_t)j * 4097;
                float w0 = w0p[0];
                float w1 = w0p[(size_t)OSC * 4097];
                float w2 = w0p[(size_t)2 * OSC * 4097];
                float hx1 = g_hx[0], hx2 = g_hx[1];
                acc[0] += w0 * hx1; acc[1] += w1 * hx1; acc[2] += w2 * hx1;
                acc[3] += w0 * hx2; acc[4] += w1 * hx2; acc[5] += w2 * hx2;
            }
        }
        float s[12];
        blockReduce<12>(acc, s);
        if (tid == 0) {
#pragma unroll
            for (int i = 0; i < 12; i++) g_hp[j][i] = s[i];
        }
    }
}

// ---------------- K2: mout rows + k/f heads (no internal deps) ----------------
__global__ __launch_bounds__(NTHR) void k_mout(
    const float* __restrict__ w, const float* __restrict__ bias,
    const float* __restrict__ k_ow, const float* __restrict__ k_ob,
    const float* __restrict__ f_ow, const float* __restrict__ f_ob,
    float* __restrict__ out)
{
    const int b = blockIdx.x;
    const int tid = threadIdx.x;
    if (b < 4096) {
        const int r = b;
        const float* wr = w + (size_t)r * MH;
        int d0 = tid << 2;
        float4 a0 = ldw(wr + d0),        a1 = ldw(wr + d0 + 1024);
        float4 a2 = ldw(wr + d0 + 2048), a3 = ldw(wr + d0 + 3072);
        float4 m0 = ldx(g_mnew + d0),        m1 = ldx(g_mnew + d0 + 1024);
        float4 m2 = ldx(g_mnew + d0 + 2048), m3 = ldx(g_mnew + d0 + 3072);
        float acc[1];
        acc[0] = dot4(a0, m0) + dot4(a1, m1) + dot4(a2, m2) + dot4(a3, m3);
        float s[1];
        blockReduce<1>(acc, s);
        if (tid == 0) {
            float v = s[0] + bias[r];
            if (r < OSC) {
#pragma unroll
                for (int o = 0; o < 4; o++) g_so1[o * SH_P + o + r] = v;
            } else {
                int rr = r - OSC;
#pragma unroll
                for (int o = 0; o < 4; o++) g_so2[o * SH_P + o + rr] = v;
            }
        }
    } else {
        const int hb = b - 4096;
        const float* vec;
        const float* hw;
        const float* bp;
        int oidx;
        switch (hb) {
            case 0:  vec = g_k1new; hw = k_ow; bp = k_ob; oidx = 1; break;
            case 1:  vec = g_f1new; hw = f_ow; bp = f_ob; oidx = 2; break;
            case 2:  vec = g_k2new; hw = k_ow; bp = k_ob; oidx = 4; break;
            default: vec = g_f2new; hw = f_ow; bp = f_ob; oidx = 5; break;
        }
        int d0 = tid << 2;
        float4 a0 = ldx(hw + d0), a1 = ldx(hw + d0 + 1024);
        float4 v0 = ldx(vec + d0), v1 = ldx(vec + d0 + 1024);
        float acc[1];
        acc[0] = dot4(a0, v0) + dot4(a1, v1);
        float s[1];
        blockReduce<1>(acc, s);
        if (tid == 0) out[oidx] = s[0] + bp[0];
    }
}

// ---------------- K3: h_dep — TWO rows per block sharing x (1:1 w:x ratio) ----------------
// block b: gate g = b >> 10, j = b & 1023. Rows g*2048+j and g*2048+j+1024 (same class).
__global__ __launch_bounds__(NTHR) void k_hdepG2(
    const float* __restrict__ h_wih)
{
    const int b = blockIdx.x;
    const int g = b >> 10;
    const int j = b & 1023;
    const int j2 = j + 1024;
    const int tid = threadIdx.x;
    const int a = (j + 1) & 3;           // same class for j and j2
    const int head = (4 - a) & 3;
    const float* w1row = h_wih + (size_t)(g * OSC + j) * 4097 + 1;
    const float* w2row = h_wih + (size_t)(g * OSC + j2) * 4097 + 1;
    const float* xo1 = g_so1 + a * SH_P + a;
    const float* xo2 = g_so2 + a * SH_P + a;
    const int nv = (2048 - head) >> 2;   // 511 or 512

    // acc: {w1.xo1, w1.xo2, w2.xo1, w2.xo2}
    float acc[4] = {0, 0, 0, 0};
    int e0 = head + (tid << 2);
    float4 wa0 = ldw(w1row + e0);
    float4 wb0 = ldw(w2row + e0);
    float4 p0 = ldx(xo1 + e0), q0 = ldx(xo2 + e0);
    bool ok1 = (tid + NTHR < nv);
    int e1 = e0 + (NTHR << 2);
    if (ok1) {
        float4 wa1 = ldw(w1row + e1);
        float4 wb1 = ldw(w2row + e1);
        float4 p1 = ldx(xo1 + e1), q1 = ldx(xo2 + e1);
        acc[0] += dot4(wa1, p1); acc[1] += dot4(wa1, q1);
        acc[2] += dot4(wb1, p1); acc[3] += dot4(wb1, q1);
    }
    acc[0] += dot4(wa0, p0); acc[1] += dot4(wa0, q0);
    acc[2] += dot4(wb0, p0); acc[3] += dot4(wb0, q0);
    if (tid < head) {
        float xa = xo1[tid], xb = xo2[tid];
        float v1 = w1row[tid], v2 = w2row[tid];
        acc[0] += v1 * xa; acc[1] += v1 * xb;
        acc[2] += v2 * xa; acc[3] += v2 * xb;
    }
    {
        const int tstart = head + (nv << 2);
        const int tcount = 2048 - tstart;    // 0..3
        if (tid >= 32 && tid - 32 < tcount) {
            int t = tstart + (tid - 32);
            float xa = xo1[t], xb = xo2[t];
            float v1 = w1row[t], v2 = w2row[t];
            acc[0] += v1 * xa; acc[1] += v1 * xb;
            acc[2] += v2 * xa; acc[3] += v2 * xb;
        }
    }

    float s[4];
    blockReduce<4>(acc, s);
    if (tid == 0) {
        g_hq[j][2 * g]      = s[0];
        g_hq[j][2 * g + 1]  = s[1];
        g_hq[j2][2 * g]     = s[2];
        g_hq[j2][2 * g + 1] = s[3];
    }
}

// ---------------- K4: fused gates + h-head dots (8 blocks + ticket finisher) ----------------
__global__ __launch_bounds__(NTHR) void k_gh(
    const float* __restrict__ h_bih, const float* __restrict__ h_bhh,
    const float* __restrict__ h1s, const float* __restrict__ h2s,
    const float* __restrict__ h_ow, const float* __restrict__ h_ob,
    float* __restrict__ out)
{
    const int j = blockIdx.x * NTHR + threadIdx.x;   // 8 blocks -> 2048
    const float4* hp4 = reinterpret_cast<const float4*>(g_hp[j]);
    const float4* hq4 = reinterpret_cast<const float4*>(g_hq[j]);
    float4 pa = hp4[0], pb = hp4[1], pc = hp4[2];
    float4 qa = hq4[0], qb = hq4[1];
    // hp: [gi1 r z n | gi2 r z n | gh1 r z n | gh2 r z n]
    // hq: [r_s1 r_s2 z_s1 z_s2 n_s1 n_s2 _ _]  (index 2g+s)
    float gi1r = pa.x + qa.x;
    float gi1z = pa.y + qa.z;
    float gi1n = pa.z + qb.x;
    float gi2r = pa.w + qa.y;
    float gi2z = pb.x + qa.w;
    float gi2n = pb.y + qb.y;
    float gh1r = pb.z, gh1z = pb.w, gh1n = pc.x;
    float gh2r = pc.y, gh2z = pc.z, gh2n = pc.w;
    float br = h_bih[j], bz = h_bih[OSC + j], bn = h_bih[2 * OSC + j];
    float cr = h_bhh[j], cz = h_bhh[OSC + j], cn = h_bhh[2 * OSC + j];
    float h1n_val, h2n_val;
    {
        float r = sigm(gi1r + br + gh1r + cr);
        float z = sigm(gi1z + bz + gh1z + cz);
        float n = tanhf(gi1n + bn + r * (gh1n + cn));
        h1n_val = (1.0f - z) * n + z * h1s[j];
    }
    {
        float r = sigm(gi2r + br + gh2r + cr);
        float z = sigm(gi2z + bz + gh2z + cz);
        float n = tanhf(gi2n + bn + r * (gh2n + cn));
        h2n_val = (1.0f - z) * n + z * h2s[j];
    }
    float wv = h_ow[j];
    float acc[2] = { wv * h1n_val, wv * h2n_val };
    float s[2];
    blockReduce<2>(acc, s);
    if (threadIdx.x == 0) {
        g_ghp[blockIdx.x][0] = s[0];
        g_ghp[blockIdx.x][1] = s[1];
        __threadfence();
        unsigned ticket = atomicAdd(&g_ghc, 1u);
        if (ticket == 7u) {
            __threadfence();
            float t0 = 0.0f, t1 = 0.0f;
#pragma unroll
            for (int bbl = 0; bbl < 8; bbl++) {
                t0 += __ldcg(&g_ghp[bbl][0]);
                t1 += __ldcg(&g_ghp[bbl][1]);
            }
            float hb = h_ob[0];
            out[0] = t0 + hb;
            out[3] = t1 + hb;
        }
    }
}

// ---------------- launch ----------------
extern "C" void kernel_launch(void* const* d_in, const int* in_sizes, int n_in,
                              void* d_out, int out_size)
{
    const float* x      = (const float*)d_in[0];
    const float* m_s    = (const float*)d_in[1];
    const float* h1_s   = (const float*)d_in[2];
    const float* h2_s   = (const float*)d_in[3];
    const float* k1_s   = (const float*)d_in[4];
    const float* k2_s   = (const float*)d_in[5];
    const float* f1_s   = (const float*)d_in[6];
    const float* f2_s   = (const float*)d_in[7];
    const float* m_wih  = (const float*)d_in[8];
    const float* m_whh  = (const float*)d_in[9];
    const float* m_bih  = (const float*)d_in[10];
    const float* m_bhh  = (const float*)d_in[11];
    const float* m_ow   = (const float*)d_in[12];
    const float* m_ob   = (const float*)d_in[13];
    const float* h_wih  = (const float*)d_in[14];
    const float* h_whh  = (const float*)d_in[15];
    const float* h_bih  = (const float*)d_in[16];
    const float* h_bhh  = (const float*)d_in[17];
    const float* h_ow   = (const float*)d_in[18];
    const float* h_ob   = (const float*)d_in[19];
    const float* k_wih  = (const float*)d_in[20];
    const float* k_whh  = (const float*)d_in[21];
    const float* k_bih  = (const float*)d_in[22];
    const float* k_bhh  = (const float*)d_in[23];
    const float* k_ow   = (const float*)d_in[24];
    const float* k_ob   = (const float*)d_in[25];
    const float* f_wih  = (const float*)d_in[26];
    const float* f_whh  = (const float*)d_in[27];
    const float* f_bih  = (const float*)d_in[28];
    const float* f_bhh  = (const float*)d_in[29];
    const float* f_ow   = (const float*)d_in[30];
    const float* f_ob   = (const float*)d_in[31];
    float* out = (float*)d_out;

    k_prep<<<(4 * OSC) / NTHR, NTHR>>>(x, h1_s, h2_s, k1_s, k2_s, f1_s, f2_s);
    k_main<<<10240, NTHR>>>(m_s, h1_s, h2_s, k1_s, k2_s, f1_s, f2_s,
                            m_wih, m_whh, m_bih, m_bhh,
                            h_wih, h_whh,
                            k_wih, k_whh, k_bih, k_bhh,
                            f_wih, f_whh, f_bih, f_bhh);
    k_mout<<<4100, NTHR>>>(m_ow, m_ob, k_ow, k_ob, f_ow, f_ob, out);
    k_hdepG2<<<3 * 1024, NTHR>>>(h_wih);
    k_gh<<<OSC / NTHR, NTHR>>>(h_bih, h_bhh, h1_s, h2_s, h_ow, h_ob, out);
}